// round 4
// baseline (speedup 1.0000x reference)
#include <cuda_runtime.h>

#define BB 4096

constexpr int S1N = 32 * 14 * 14;   // 6272
constexpr int S2N = 64 * 7 * 7;     // 3136
constexpr int S3N = 64 * 7 * 7;     // 3136
constexpr int S4N = 256;

// ---------------- scratch (device globals; allocation-free) ----------------
__device__ float g_S1[2][S1N * BB];
__device__ float g_S2[2][S2N * BB];
__device__ float g_S3[2][S3N * BB];
__device__ float g_S4[2][S4N * BB];
__device__ float g_D1[S1N * BB];        // conv1(x)+b1, batch-minor
__device__ float g_XT[784 * BB];        // x transposed to [pixel][batch]
__device__ float g_w2a[64 * 9 * 32];    // [o][t][c]   (for tconv2: contiguous c)
__device__ float g_w2b[32 * 9 * 64];    // [c][t][o]   (for conv2:  contiguous o)
__device__ float g_w3a[64 * 9 * 64];    // [o][t][m]   (for conv3:  contiguous m)
__device__ float g_w3b[64 * 9 * 64];    // [m][t][o]   (for tconv3: contiguous o)
__device__ float g_w4t[3136 * 256];     // [k][j]      (for K4:     contiguous j)
__device__ float g_w4r[49 * 256 * 64];  // [pos][j][c] (for K3 fc:  contiguous c)

// ---------------- init / prep ----------------
__global__ void zero_state() {
    int stride = gridDim.x * blockDim.x;
    for (int i = blockIdx.x * blockDim.x + threadIdx.x; i < S1N * BB; i += stride) {
        g_S1[0][i] = 0.f;
        if (i < S2N * BB) { g_S2[0][i] = 0.f; g_S3[0][i] = 0.f; }
        if (i < S4N * BB) { g_S4[0][i] = 0.f; }
    }
}

__global__ void transpose_x(const float* __restrict__ x) {
    __shared__ float tile[32][33];
    int p0 = blockIdx.x * 32, b0 = blockIdx.y * 32;
    int tx = threadIdx.x, ty = threadIdx.y;
    for (int i = ty; i < 32; i += 8) {
        int p = p0 + tx;
        tile[i][tx] = (p < 784) ? x[(b0 + i) * 784 + p] : 0.f;
    }
    __syncthreads();
    for (int i = ty; i < 32; i += 8) {
        int p = p0 + i;
        if (p < 784) g_XT[p * BB + b0 + tx] = tile[tx][i];
    }
}

__global__ void prep_weights(const float* __restrict__ w2,
                             const float* __restrict__ w3,
                             const float* __restrict__ w4) {
    int stride = gridDim.x * blockDim.x;
    for (int idx = blockIdx.x * blockDim.x + threadIdx.x; idx < 802816; idx += stride) {
        if (idx < 18432) {  // w2: [o=64][c=32][t=9]
            int o = idx / 288, r = idx % 288, c = r / 9, t = r % 9;
            float v = w2[idx];
            g_w2a[(o * 9 + t) * 32 + c] = v;
            g_w2b[(c * 9 + t) * 64 + o] = v;
        }
        if (idx < 36864) {  // w3: [m=64][o=64][t=9]
            int m = idx / 576, r = idx % 576, o = r / 9, t = r % 9;
            float v = w3[idx];
            g_w3a[(o * 9 + t) * 64 + m] = v;
            g_w3b[(m * 9 + t) * 64 + o] = v;
        }
        {   // w4: [j=256][k=3136]
            int j = idx / 3136, k = idx % 3136;
            float v = w4[idx];
            g_w4t[k * 256 + j] = v;
            int c = k / 49, pos = k % 49;
            g_w4r[(pos * 256 + j) * 64 + c] = v;
        }
    }
}

// d1[c,u,v,b] = b1[c] + sum_{t} w1[c,t] * x[b, 2u+di-1, 2v+dj-1]
__global__ void compute_d1(const float* __restrict__ w1, const float* __restrict__ b1) {
    int b = blockIdx.x * 256 + threadIdx.x;
    int pos = blockIdx.y;
    int u = pos / 14, v = pos % 14;
    int c = blockIdx.z;
    float acc = b1[c];
#pragma unroll
    for (int di = 0; di < 3; di++) {
        int h = 2 * u + di - 1;
        if (h < 0 || h >= 28) continue;
#pragma unroll
        for (int dj = 0; dj < 3; dj++) {
            int w = 2 * v + dj - 1;
            if (w < 0 || w >= 28) continue;
            acc = fmaf(w1[c * 9 + di * 3 + dj], g_XT[(h * 28 + w) * BB + b], acc);
        }
    }
    g_D1[(c * 196 + pos) * BB + b] = acc;
}

// ---------------- K1: s1' = 0.5*(s1 + d1 + conv2^T(s2)) ----------------
__global__ void __launch_bounds__(256) k1_update(int cur) {
    __shared__ float ws[64 * 9 * 8];  // w2a slice for 8 input channels
    const int tid = threadIdx.x;
    const int c0 = blockIdx.z * 8;
    for (int i = tid; i < 576; i += 256) {
        const float* src = &g_w2a[i * 32 + c0];
        float* dst = &ws[i * 8];
#pragma unroll
        for (int r = 0; r < 8; r++) dst[r] = src[r];
    }
    __syncthreads();

    const int b = blockIdx.x * 256 + tid;
    const int pos = blockIdx.y;
    const int u = pos / 14, v = pos % 14;

    // valid (di, p) candidates per dimension (stride-2 transposed conv, k=3, pad=1)
    int p0, p1, wu0, wu1; bool vu0, vu1;
    if (u & 1) { p0 = (u + 1) >> 1; wu0 = 0; vu0 = (p0 < 7);
                 p1 = (u - 1) >> 1; wu1 = 2; vu1 = true; }
    else       { p0 = u >> 1;       wu0 = 1; vu0 = true;
                 p1 = 0;            wu1 = 0; vu1 = false; }
    int q0, q1, wv0, wv1; bool vv0, vv1;
    if (v & 1) { q0 = (v + 1) >> 1; wv0 = 0; vv0 = (q0 < 7);
                 q1 = (v - 1) >> 1; wv1 = 2; vv1 = true; }
    else       { q0 = v >> 1;       wv0 = 1; vv0 = true;
                 q1 = 0;            wv1 = 0; vv1 = false; }

    const int off00 = (p0 * 7 + q0) * BB, wa00 = (wu0 * 3 + wv0) * 8; const bool ok00 = vu0 && vv0;
    const int off01 = (p0 * 7 + q1) * BB, wa01 = (wu0 * 3 + wv1) * 8; const bool ok01 = vu0 && vv1;
    const int off10 = (p1 * 7 + q0) * BB, wa10 = (wu1 * 3 + wv0) * 8; const bool ok10 = vu1 && vv0;
    const int off11 = (p1 * 7 + q1) * BB, wa11 = (wu1 * 3 + wv1) * 8; const bool ok11 = vu1 && vv1;

    const float* __restrict__ S2 = g_S2[cur];
    float acc[8];
#pragma unroll
    for (int r = 0; r < 8; r++) acc[r] = 0.f;

#pragma unroll 2
    for (int o = 0; o < 64; o++) {
        const float* base = S2 + o * 49 * BB + b;
        const float* wb = ws + o * 72;
        if (ok00) { float sv = base[off00]; const float* wp = wb + wa00;
#pragma unroll
            for (int r = 0; r < 8; r++) acc[r] = fmaf(sv, wp[r], acc[r]); }
        if (ok01) { float sv = base[off01]; const float* wp = wb + wa01;
#pragma unroll
            for (int r = 0; r < 8; r++) acc[r] = fmaf(sv, wp[r], acc[r]); }
        if (ok10) { float sv = base[off10]; const float* wp = wb + wa10;
#pragma unroll
            for (int r = 0; r < 8; r++) acc[r] = fmaf(sv, wp[r], acc[r]); }
        if (ok11) { float sv = base[off11]; const float* wp = wb + wa11;
#pragma unroll
            for (int r = 0; r < 8; r++) acc[r] = fmaf(sv, wp[r], acc[r]); }
    }

    const float* __restrict__ S1i = g_S1[cur];
    float* __restrict__ S1o = g_S1[cur ^ 1];
    const int oidx = (c0 * 196 + pos) * BB + b;
#pragma unroll
    for (int r = 0; r < 8; r++) {
        int ii = oidx + r * (196 * BB);
        S1o[ii] = 0.5f * (S1i[ii] + g_D1[ii] + acc[r]);
    }
}

// ---------------- K2: s2' = 0.5*(s2 + conv2(s1)+b2 + conv3^T(s3)) ----------------
// MODE 0: full update.  MODE 1: write conv2(s1)+b2 only (energy readout).
template <int MODE>
__global__ void __launch_bounds__(256) k2_kernel(int cur, const float* __restrict__ b2) {
    __shared__ float ws2[288 * 8];
    __shared__ float ws3[576 * 8];
    const int tid = threadIdx.x;
    const int o0 = blockIdx.z * 8;
    for (int i = tid; i < 288; i += 256) {
        const float* src = &g_w2b[i * 64 + o0];
        float* dst = &ws2[i * 8];
#pragma unroll
        for (int r = 0; r < 8; r++) dst[r] = src[r];
    }
    if (MODE == 0) {
        for (int i = tid; i < 576; i += 256) {
            const float* src = &g_w3b[i * 64 + o0];
            float* dst = &ws3[i * 8];
#pragma unroll
            for (int r = 0; r < 8; r++) dst[r] = src[r];
        }
    }
    __syncthreads();

    const int b = blockIdx.x * 256 + tid;
    const int pos = blockIdx.y;
    const int p = pos / 7, q = pos % 7;

    float acc[8];
#pragma unroll
    for (int r = 0; r < 8; r++) acc[r] = 0.f;

    // conv2(s1): stride 2
    {
        int off[9]; bool ok[9];
#pragma unroll
        for (int di = 0; di < 3; di++)
#pragma unroll
            for (int dj = 0; dj < 3; dj++) {
                int h = 2 * p + di - 1, w = 2 * q + dj - 1;
                ok[di * 3 + dj] = (h >= 0) && (w >= 0);
                off[di * 3 + dj] = (h * 14 + w) * BB;
            }
        const float* __restrict__ S1 = g_S1[cur];
#pragma unroll 2
        for (int c = 0; c < 32; c++) {
            const float* base = S1 + c * 196 * BB + b;
            const float* wb = ws2 + c * 72;
#pragma unroll
            for (int t = 0; t < 9; t++) {
                if (ok[t]) {
                    float sv = base[off[t]];
                    const float* wp = wb + t * 8;
#pragma unroll
                    for (int r = 0; r < 8; r++) acc[r] = fmaf(sv, wp[r], acc[r]);
                }
            }
        }
    }

    // conv3^T(s3): stride 1, flipped taps
    if (MODE == 0) {
        int off[9]; bool ok[9];
#pragma unroll
        for (int di = 0; di < 3; di++)
#pragma unroll
            for (int dj = 0; dj < 3; dj++) {
                int rr = p + 1 - di, cc = q + 1 - dj;
                ok[di * 3 + dj] = (rr >= 0) && (rr < 7) && (cc >= 0) && (cc < 7);
                off[di * 3 + dj] = (rr * 7 + cc) * BB;
            }
        const float* __restrict__ S3 = g_S3[cur];
#pragma unroll 2
        for (int m = 0; m < 64; m++) {
            const float* base = S3 + m * 49 * BB + b;
            const float* wb = ws3 + m * 72;
#pragma unroll
            for (int t = 0; t < 9; t++) {
                if (ok[t]) {
                    float sv = base[off[t]];
                    const float* wp = wb + t * 8;
#pragma unroll
                    for (int r = 0; r < 8; r++) acc[r] = fmaf(sv, wp[r], acc[r]);
                }
            }
        }
    }

    const float* __restrict__ S2i = g_S2[cur];
    float* __restrict__ outp = g_S2[cur ^ 1];
    const int oidx = (o0 * 49 + pos) * BB + b;
#pragma unroll
    for (int r = 0; r < 8; r++) {
        int ii = oidx + r * (49 * BB);
        if (MODE == 0) outp[ii] = 0.5f * (S2i[ii] + acc[r] + b2[o0 + r]);
        else           outp[ii] = acc[r] + b2[o0 + r];
    }
}

// ---------------- K3: s3' = 0.5*(s3 + conv3(s2)+b3 + W4^T s4) ----------------
// MODE 0: full update.  MODE 1: write conv3(s2)+b3 only.
template <int MODE>
__global__ void __launch_bounds__(256) k3_kernel(int cur, const float* __restrict__ b3) {
    __shared__ float ws3[576 * 8];
    __shared__ float ws4[256 * 8];
    const int tid = threadIdx.x;
    const int c0 = blockIdx.z * 8;
    const int pos = blockIdx.y;
    for (int i = tid; i < 576; i += 256) {
        const float* src = &g_w3a[i * 64 + c0];
        float* dst = &ws3[i * 8];
#pragma unroll
        for (int r = 0; r < 8; r++) dst[r] = src[r];
    }
    if (MODE == 0) {
        for (int j = tid; j < 256; j += 256) {
            const float* src = &g_w4r[(pos * 256 + j) * 64 + c0];
            float* dst = &ws4[j * 8];
#pragma unroll
            for (int r = 0; r < 8; r++) dst[r] = src[r];
        }
    }
    __syncthreads();

    const int b = blockIdx.x * 256 + tid;
    const int p = pos / 7, q = pos % 7;

    float acc[8];
#pragma unroll
    for (int r = 0; r < 8; r++) acc[r] = 0.f;

    // conv3(s2): stride 1
    {
        int off[9]; bool ok[9];
#pragma unroll
        for (int di = 0; di < 3; di++)
#pragma unroll
            for (int dj = 0; dj < 3; dj++) {
                int h = p + di - 1, w = q + dj - 1;
                ok[di * 3 + dj] = (h >= 0) && (h < 7) && (w >= 0) && (w < 7);
                off[di * 3 + dj] = (h * 7 + w) * BB;
            }
        const float* __restrict__ S2 = g_S2[cur];
#pragma unroll 2
        for (int o = 0; o < 64; o++) {
            const float* base = S2 + o * 49 * BB + b;
            const float* wb = ws3 + o * 72;
#pragma unroll
            for (int t = 0; t < 9; t++) {
                if (ok[t]) {
                    float sv = base[off[t]];
                    const float* wp = wb + t * 8;
#pragma unroll
                    for (int r = 0; r < 8; r++) acc[r] = fmaf(sv, wp[r], acc[r]);
                }
            }
        }
    }

    // W4^T s4
    if (MODE == 0) {
        const float* __restrict__ S4 = g_S4[cur];
#pragma unroll 4
        for (int j = 0; j < 256; j++) {
            float sv = S4[j * BB + b];
            const float* wp = &ws4[j * 8];
#pragma unroll
            for (int r = 0; r < 8; r++) acc[r] = fmaf(sv, wp[r], acc[r]);
        }
    }

    const float* __restrict__ S3i = g_S3[cur];
    float* __restrict__ outp = g_S3[cur ^ 1];
    const int oidx = (c0 * 49 + pos) * BB + b;
#pragma unroll
    for (int r = 0; r < 8; r++) {
        int ii = oidx + r * (49 * BB);
        if (MODE == 0) outp[ii] = 0.5f * (S3i[ii] + acc[r] + b3[c0 + r]);
        else           outp[ii] = acc[r] + b3[c0 + r];
    }
}

// ---------------- K4: s4' = 0.5*(s4 + W4 s3 + b4) ----------------
// MODE 0: full update.  MODE 1: write W4 s3 + b4 only.
template <int MODE>
__global__ void __launch_bounds__(256) k4_kernel(int cur, const float* __restrict__ b4) {
    __shared__ float ws[448 * 8];
    const int tid = threadIdx.x;
    const int j0 = blockIdx.y * 8;
    const int b = blockIdx.x * 256 + tid;
    const float* __restrict__ S3 = g_S3[cur];

    float acc[8];
#pragma unroll
    for (int r = 0; r < 8; r++) acc[r] = 0.f;

    for (int k0 = 0; k0 < 3136; k0 += 448) {
        __syncthreads();
        for (int i = tid; i < 448; i += 256) {
            const float* src = &g_w4t[(k0 + i) * 256 + j0];
            float* dst = &ws[i * 8];
#pragma unroll
            for (int r = 0; r < 8; r++) dst[r] = src[r];
        }
        __syncthreads();
#pragma unroll 4
        for (int kk = 0; kk < 448; kk++) {
            float sv = S3[(k0 + kk) * BB + b];
            const float* wp = &ws[kk * 8];
#pragma unroll
            for (int r = 0; r < 8; r++) acc[r] = fmaf(sv, wp[r], acc[r]);
        }
    }

    const float* __restrict__ S4i = g_S4[cur];
    float* __restrict__ outp = g_S4[cur ^ 1];
#pragma unroll
    for (int r = 0; r < 8; r++) {
        int ii = (j0 + r) * BB + b;
        if (MODE == 0) outp[ii] = 0.5f * (S4i[ii] + acc[r] + b4[j0 + r]);
        else           outp[ii] = acc[r] + b4[j0 + r];
    }
}

// ---------------- energy readout ----------------
__global__ void energy_zero(float* __restrict__ out) {
    int b = blockIdx.x * 256 + threadIdx.x;
    out[b] = 0.f;
}

// grid (16, 8): 8 position slices per batch tile, atomicAdd partials.
__global__ void energy_partial(const float* __restrict__ vb, int fin,
                               float* __restrict__ out) {
    const int b = blockIdx.x * 256 + threadIdx.x;
    const int s = blockIdx.y;  // 0..7
    const float* __restrict__ S1 = g_S1[fin];
    const float* __restrict__ S2 = g_S2[fin];
    const float* __restrict__ S3 = g_S3[fin];
    const float* __restrict__ S4 = g_S4[fin];
    const float* __restrict__ F2 = g_S2[fin ^ 1];
    const float* __restrict__ F3 = g_S3[fin ^ 1];
    const float* __restrict__ F4 = g_S4[fin ^ 1];

    double e = 0.0;
    if (s == 0) {
        for (int p = 0; p < 784; p++) {
            float xv = g_XT[p * BB + b];
            float term = 0.5f * xv * xv - vb[p] * xv;
            e += (double)term;
        }
        for (int i = 0; i < 256; i++) {
            float sv = S4[i * BB + b];
            float term = 0.5f * sv * sv - sv * F4[i * BB + b];
            e += (double)term;
        }
    }
    {
        int i0 = s * 784;
        for (int i = i0; i < i0 + 784; i++) {
            float sv = S1[i * BB + b];
            float term = 0.5f * sv * sv - sv * g_D1[i * BB + b];
            e += (double)term;
        }
    }
    if (s < 4) {
        int i0 = s * 784;
        for (int i = i0; i < i0 + 784; i++) {
            float sv = S2[i * BB + b];
            float term = 0.5f * sv * sv - sv * F2[i * BB + b];
            e += (double)term;
        }
    } else {
        int i0 = (s - 4) * 784;
        for (int i = i0; i < i0 + 784; i++) {
            float sv = S3[i * BB + b];
            float term = 0.5f * sv * sv - sv * F3[i * BB + b];
            e += (double)term;
        }
    }
    atomicAdd(&out[b], (float)e);
}

// ---------------- launcher ----------------
extern "C" void kernel_launch(void* const* d_in, const int* in_sizes, int n_in,
                              void* d_out, int out_size) {
    const float* x  = (const float*)d_in[0];
    const float* vb = (const float*)d_in[1];
    const float* w1 = (const float*)d_in[2];
    const float* b1 = (const float*)d_in[3];
    const float* w2 = (const float*)d_in[4];
    const float* b2 = (const float*)d_in[5];
    const float* w3 = (const float*)d_in[6];
    const float* b3 = (const float*)d_in[7];
    const float* w4 = (const float*)d_in[8];
    const float* b4 = (const float*)d_in[9];
    float* out = (float*)d_out;

    zero_state<<<2048, 256>>>();
    transpose_x<<<dim3(25, 128), dim3(32, 8)>>>(x);
    prep_weights<<<1024, 256>>>(w2, w3, w4);
    compute_d1<<<dim3(16, 196, 32), 256>>>(w1, b1);

    int cur = 0;
    for (int t = 0; t < 50; t++) {
        k1_update<<<dim3(16, 196, 4), 256>>>(cur);
        k2_kernel<0><<<dim3(16, 49, 8), 256>>>(cur, b2);
        k3_kernel<0><<<dim3(16, 49, 8), 256>>>(cur, b3);
        k4_kernel<0><<<dim3(16, 32, 1), 256>>>(cur, b4);
        cur ^= 1;
    }

    // forward-only passes at the fixed point into the free ping-pong buffers
    k2_kernel<1><<<dim3(16, 49, 8), 256>>>(cur, b2);
    k3_kernel<1><<<dim3(16, 49, 8), 256>>>(cur, b3);
    k4_kernel<1><<<dim3(16, 32, 1), 256>>>(cur, b4);

    energy_zero<<<16, 256>>>(out);
    energy_partial<<<dim3(16, 8), 256>>>(vb, cur, out);
}

// round 6
// speedup vs baseline: 1.2138x; 1.2138x over previous
#include <cuda_runtime.h>

#define BB 4096
#define PB 2048   // pairs per row (BB/2)

constexpr int S1N = 32 * 14 * 14;   // 6272
constexpr int S2N = 64 * 7 * 7;     // 3136
constexpr int S3N = 64 * 7 * 7;     // 3136
constexpr int S4N = 256;

typedef unsigned long long ull;

// ---------------- packed f32x2 helpers (Blackwell FFMA2 path) ----------------
__device__ __forceinline__ ull fma2(ull a, ull b, ull c) {
    ull d; asm("fma.rn.f32x2 %0, %1, %2, %3;" : "=l"(d) : "l"(a), "l"(b), "l"(c)); return d;
}
__device__ __forceinline__ ull add2(ull a, ull b) {
    ull d; asm("add.rn.f32x2 %0, %1, %2;" : "=l"(d) : "l"(a), "l"(b)); return d;
}
__device__ __forceinline__ ull mul2(ull a, ull b) {
    ull d; asm("mul.rn.f32x2 %0, %1, %2;" : "=l"(d) : "l"(a), "l"(b)); return d;
}
// duplicate one float into both halves of a 64-bit pair (1 SASS instr)
__device__ __forceinline__ ull pk(float x) {
    ull d; unsigned u = __float_as_uint(x);
    asm("mov.b64 %0, {%1, %1};" : "=l"(d) : "r"(u)); return d;
}

// ---------------- scratch (device globals; allocation-free) ----------------
__device__ float g_S1[2][S1N * BB];
__device__ float g_S2[2][S2N * BB];
__device__ float g_S3[2][S3N * BB];
__device__ float g_S4[2][S4N * BB];
__device__ float g_D1[S1N * BB];        // conv1(x)+b1, batch-minor
__device__ float g_XT[784 * BB];        // x transposed to [pixel][batch]
__device__ float g_w2a[64 * 9 * 32];    // [o][t][c]   (for tconv2: contiguous c)
__device__ float g_w2b[32 * 9 * 64];    // [c][t][o]   (for conv2:  contiguous o)
__device__ float g_w3a[64 * 9 * 64];    // [o][t][m]   (for conv3:  contiguous m)
__device__ float g_w3b[64 * 9 * 64];    // [m][t][o]   (for tconv3: contiguous o)
__device__ float g_w4t[3136 * 256];     // [k][j]      (for K4:     contiguous j)
__device__ float g_w4r[49 * 256 * 64];  // [pos][j][c] (for K3 fc:  contiguous c)

// ---------------- init / prep ----------------
__global__ void zero_state() {
    int stride = gridDim.x * blockDim.x;
    for (int i = blockIdx.x * blockDim.x + threadIdx.x; i < S1N * BB; i += stride) {
        g_S1[0][i] = 0.f;
        if (i < S2N * BB) { g_S2[0][i] = 0.f; g_S3[0][i] = 0.f; }
        if (i < S4N * BB) { g_S4[0][i] = 0.f; }
    }
}

__global__ void transpose_x(const float* __restrict__ x) {
    __shared__ float tile[32][33];
    int p0 = blockIdx.x * 32, b0 = blockIdx.y * 32;
    int tx = threadIdx.x, ty = threadIdx.y;
    for (int i = ty; i < 32; i += 8) {
        int p = p0 + tx;
        tile[i][tx] = (p < 784) ? x[(b0 + i) * 784 + p] : 0.f;
    }
    __syncthreads();
    for (int i = ty; i < 32; i += 8) {
        int p = p0 + i;
        if (p < 784) g_XT[p * BB + b0 + tx] = tile[tx][i];
    }
}

__global__ void prep_weights(const float* __restrict__ w2,
                             const float* __restrict__ w3,
                             const float* __restrict__ w4) {
    int stride = gridDim.x * blockDim.x;
    for (int idx = blockIdx.x * blockDim.x + threadIdx.x; idx < 802816; idx += stride) {
        if (idx < 18432) {  // w2: [o=64][c=32][t=9]
            int o = idx / 288, r = idx % 288, c = r / 9, t = r % 9;
            float v = w2[idx];
            g_w2a[(o * 9 + t) * 32 + c] = v;
            g_w2b[(c * 9 + t) * 64 + o] = v;
        }
        if (idx < 36864) {  // w3: [m=64][o=64][t=9]
            int m = idx / 576, r = idx % 576, o = r / 9, t = r % 9;
            float v = w3[idx];
            g_w3a[(o * 9 + t) * 64 + m] = v;
            g_w3b[(m * 9 + t) * 64 + o] = v;
        }
        {   // w4: [j=256][k=3136]
            int j = idx / 3136, k = idx % 3136;
            float v = w4[idx];
            g_w4t[k * 256 + j] = v;
            int c = k / 49, pos = k % 49;
            g_w4r[(pos * 256 + j) * 64 + c] = v;
        }
    }
}

// d1[c,u,v,b] = b1[c] + sum_{t} w1[c,t] * x[b, 2u+di-1, 2v+dj-1]
__global__ void compute_d1(const float* __restrict__ w1, const float* __restrict__ b1) {
    int b = blockIdx.x * 256 + threadIdx.x;
    int pos = blockIdx.y;
    int u = pos / 14, v = pos % 14;
    int c = blockIdx.z;
    float acc = b1[c];
#pragma unroll
    for (int di = 0; di < 3; di++) {
        int h = 2 * u + di - 1;
        if (h < 0 || h >= 28) continue;
#pragma unroll
        for (int dj = 0; dj < 3; dj++) {
            int w = 2 * v + dj - 1;
            if (w < 0 || w >= 28) continue;
            acc = fmaf(w1[c * 9 + di * 3 + dj], g_XT[(h * 28 + w) * BB + b], acc);
        }
    }
    g_D1[(c * 196 + pos) * BB + b] = acc;
}

// ---------------- K1: s1' = 0.5*(s1 + d1 + conv2^T(s2)) ----------------
// 2 batch elems per thread via f32x2. Weights duplicated (w,w) in smem.
__global__ void __launch_bounds__(256) k1_update(int cur) {
    __shared__ ull ws[576 * 8];  // 36.9 KB: w2a slice for 8 input channels, duplicated
    const int tid = threadIdx.x;
    const int c0 = blockIdx.z * 8;
    for (int i = tid; i < 576; i += 256) {
        const float* src = &g_w2a[i * 32 + c0];
        ull* dst = &ws[i * 8];
#pragma unroll
        for (int r = 0; r < 8; r++) dst[r] = pk(src[r]);
    }
    __syncthreads();

    const int bp = blockIdx.x * 256 + tid;   // batch-pair index 0..2047
    const int pos = blockIdx.y;
    const int u = pos / 14, v = pos % 14;

    int p0, p1, wu0, wu1; bool vu0, vu1;
    if (u & 1) { p0 = (u + 1) >> 1; wu0 = 0; vu0 = (p0 < 7);
                 p1 = (u - 1) >> 1; wu1 = 2; vu1 = true; }
    else       { p0 = u >> 1;       wu0 = 1; vu0 = true;
                 p1 = 0;            wu1 = 0; vu1 = false; }
    int q0, q1, wv0, wv1; bool vv0, vv1;
    if (v & 1) { q0 = (v + 1) >> 1; wv0 = 0; vv0 = (q0 < 7);
                 q1 = (v - 1) >> 1; wv1 = 2; vv1 = true; }
    else       { q0 = v >> 1;       wv0 = 1; vv0 = true;
                 q1 = 0;            wv1 = 0; vv1 = false; }

    const int off00 = (p0 * 7 + q0) * PB, wa00 = (wu0 * 3 + wv0) * 8; const bool ok00 = vu0 && vv0;
    const int off01 = (p0 * 7 + q1) * PB, wa01 = (wu0 * 3 + wv1) * 8; const bool ok01 = vu0 && vv1;
    const int off10 = (p1 * 7 + q0) * PB, wa10 = (wu1 * 3 + wv0) * 8; const bool ok10 = vu1 && vv0;
    const int off11 = (p1 * 7 + q1) * PB, wa11 = (wu1 * 3 + wv1) * 8; const bool ok11 = vu1 && vv1;

    const ull* __restrict__ S2 = (const ull*)g_S2[cur];
    ull acc[8];
#pragma unroll
    for (int r = 0; r < 8; r++) acc[r] = 0ull;

#pragma unroll 2
    for (int o = 0; o < 64; o++) {
        const ull* base = S2 + o * 49 * PB + bp;
        const ull* wb = ws + o * 72;
        if (ok00) { ull sv = base[off00]; const ull* wp = wb + wa00;
#pragma unroll
            for (int r = 0; r < 8; r++) acc[r] = fma2(sv, wp[r], acc[r]); }
        if (ok01) { ull sv = base[off01]; const ull* wp = wb + wa01;
#pragma unroll
            for (int r = 0; r < 8; r++) acc[r] = fma2(sv, wp[r], acc[r]); }
        if (ok10) { ull sv = base[off10]; const ull* wp = wb + wa10;
#pragma unroll
            for (int r = 0; r < 8; r++) acc[r] = fma2(sv, wp[r], acc[r]); }
        if (ok11) { ull sv = base[off11]; const ull* wp = wb + wa11;
#pragma unroll
            for (int r = 0; r < 8; r++) acc[r] = fma2(sv, wp[r], acc[r]); }
    }

    const ull* __restrict__ S1i = (const ull*)g_S1[cur];
    const ull* __restrict__ D1 = (const ull*)g_D1;
    ull* __restrict__ S1o = (ull*)g_S1[cur ^ 1];
    const ull half = pk(0.5f);
    const int oidx = (c0 * 196 + pos) * PB + bp;
#pragma unroll
    for (int r = 0; r < 8; r++) {
        int ii = oidx + r * (196 * PB);
        S1o[ii] = mul2(add2(add2(S1i[ii], D1[ii]), acc[r]), half);
    }
}

// ---------------- K2: s2' = 0.5*(s2 + conv2(s1)+b2 + conv3^T(s3)) ----------------
// MODE 0: full update.  MODE 1: write conv2(s1)+b2 only (energy readout).
template <int MODE>
__global__ void __launch_bounds__(256) k2_kernel(int cur, const float* __restrict__ b2) {
    __shared__ float ws2[288 * 8];  //  9.2 KB: conv2 weights, plain (pack on the fly)
    __shared__ ull   ws3[576 * 8];  // 36.9 KB: tconv3 weights, duplicated
    const int tid = threadIdx.x;
    const int o0 = blockIdx.z * 8;
    for (int i = tid; i < 288; i += 256) {
        const float* src = &g_w2b[i * 64 + o0];
        float* dst = &ws2[i * 8];
#pragma unroll
        for (int r = 0; r < 8; r++) dst[r] = src[r];
    }
    if (MODE == 0) {
        for (int i = tid; i < 576; i += 256) {
            const float* src = &g_w3b[i * 64 + o0];
            ull* dst = &ws3[i * 8];
#pragma unroll
            for (int r = 0; r < 8; r++) dst[r] = pk(src[r]);
        }
    }
    __syncthreads();

    const int bp = blockIdx.x * 256 + tid;
    const int pos = blockIdx.y;
    const int p = pos / 7, q = pos % 7;

    ull acc[8];
#pragma unroll
    for (int r = 0; r < 8; r++) acc[r] = 0ull;

    // conv2(s1): stride 2
    {
        int off[9]; bool ok[9];
#pragma unroll
        for (int di = 0; di < 3; di++)
#pragma unroll
            for (int dj = 0; dj < 3; dj++) {
                int h = 2 * p + di - 1, w = 2 * q + dj - 1;
                ok[di * 3 + dj] = (h >= 0) && (w >= 0);
                off[di * 3 + dj] = (h * 14 + w) * PB;
            }
        const ull* __restrict__ S1 = (const ull*)g_S1[cur];
#pragma unroll 2
        for (int c = 0; c < 32; c++) {
            const ull* base = S1 + c * 196 * PB + bp;
            const float* wb = ws2 + c * 72;
#pragma unroll
            for (int t = 0; t < 9; t++) {
                if (ok[t]) {
                    ull sv = base[off[t]];
                    const float* wp = wb + t * 8;
#pragma unroll
                    for (int r = 0; r < 8; r++) acc[r] = fma2(sv, pk(wp[r]), acc[r]);
                }
            }
        }
    }

    // conv3^T(s3): stride 1, flipped taps
    if (MODE == 0) {
        int off[9]; bool ok[9];
#pragma unroll
        for (int di = 0; di < 3; di++)
#pragma unroll
            for (int dj = 0; dj < 3; dj++) {
                int rr = p + 1 - di, cc = q + 1 - dj;
                ok[di * 3 + dj] = (rr >= 0) && (rr < 7) && (cc >= 0) && (cc < 7);
                off[di * 3 + dj] = (rr * 7 + cc) * PB;
            }
        const ull* __restrict__ S3 = (const ull*)g_S3[cur];
#pragma unroll 2
        for (int m = 0; m < 64; m++) {
            const ull* base = S3 + m * 49 * PB + bp;
            const ull* wb = ws3 + m * 72;
#pragma unroll
            for (int t = 0; t < 9; t++) {
                if (ok[t]) {
                    ull sv = base[off[t]];
                    const ull* wp = wb + t * 8;
#pragma unroll
                    for (int r = 0; r < 8; r++) acc[r] = fma2(sv, wp[r], acc[r]);
                }
            }
        }
    }

    const ull* __restrict__ S2i = (const ull*)g_S2[cur];
    ull* __restrict__ outp = (ull*)g_S2[cur ^ 1];
    const ull half = pk(0.5f);
    const int oidx = (o0 * 49 + pos) * PB + bp;
#pragma unroll
    for (int r = 0; r < 8; r++) {
        int ii = oidx + r * (49 * PB);
        ull bias = pk(b2[o0 + r]);
        if (MODE == 0) outp[ii] = mul2(add2(add2(S2i[ii], acc[r]), bias), half);
        else           outp[ii] = add2(acc[r], bias);
    }
}

// ---------------- K3: s3' = 0.5*(s3 + conv3(s2)+b3 + W4^T s4) ----------------
template <int MODE>
__global__ void __launch_bounds__(256) k3_kernel(int cur, const float* __restrict__ b3) {
    __shared__ ull   ws3[576 * 8];  // 36.9 KB duplicated
    __shared__ float ws4[256 * 8];  //  8.2 KB plain
    const int tid = threadIdx.x;
    const int c0 = blockIdx.z * 8;
    const int pos = blockIdx.y;
    for (int i = tid; i < 576; i += 256) {
        const float* src = &g_w3a[i * 64 + c0];
        ull* dst = &ws3[i * 8];
#pragma unroll
        for (int r = 0; r < 8; r++) dst[r] = pk(src[r]);
    }
    if (MODE == 0) {
        for (int j = tid; j < 256; j += 256) {
            const float* src = &g_w4r[(pos * 256 + j) * 64 + c0];
            float* dst = &ws4[j * 8];
#pragma unroll
            for (int r = 0; r < 8; r++) dst[r] = src[r];
        }
    }
    __syncthreads();

    const int bp = blockIdx.x * 256 + tid;
    const int p = pos / 7, q = pos % 7;

    ull acc[8];
#pragma unroll
    for (int r = 0; r < 8; r++) acc[r] = 0ull;

    // conv3(s2): stride 1
    {
        int off[9]; bool ok[9];
#pragma unroll
        for (int di = 0; di < 3; di++)
#pragma unroll
            for (int dj = 0; dj < 3; dj++) {
                int h = p + di - 1, w = q + dj - 1;
                ok[di * 3 + dj] = (h >= 0) && (h < 7) && (w >= 0) && (w < 7);
                off[di * 3 + dj] = (h * 7 + w) * PB;
            }
        const ull* __restrict__ S2 = (const ull*)g_S2[cur];
#pragma unroll 2
        for (int o = 0; o < 64; o++) {
            const ull* base = S2 + o * 49 * PB + bp;
            const ull* wb = ws3 + o * 72;
#pragma unroll
            for (int t = 0; t < 9; t++) {
                if (ok[t]) {
                    ull sv = base[off[t]];
                    const ull* wp = wb + t * 8;
#pragma unroll
                    for (int r = 0; r < 8; r++) acc[r] = fma2(sv, wp[r], acc[r]);
                }
            }
        }
    }

    // W4^T s4
    if (MODE == 0) {
        const ull* __restrict__ S4 = (const ull*)g_S4[cur];
#pragma unroll 4
        for (int j = 0; j < 256; j++) {
            ull sv = S4[j * PB + bp];
            const float* wp = &ws4[j * 8];
#pragma unroll
            for (int r = 0; r < 8; r++) acc[r] = fma2(sv, pk(wp[r]), acc[r]);
        }
    }

    const ull* __restrict__ S3i = (const ull*)g_S3[cur];
    ull* __restrict__ outp = (ull*)g_S3[cur ^ 1];
    const ull half = pk(0.5f);
    const int oidx = (c0 * 49 + pos) * PB + bp;
#pragma unroll
    for (int r = 0; r < 8; r++) {
        int ii = oidx + r * (49 * PB);
        ull bias = pk(b3[c0 + r]);
        if (MODE == 0) outp[ii] = mul2(add2(add2(S3i[ii], acc[r]), bias), half);
        else           outp[ii] = add2(acc[r], bias);
    }
}

// ---------------- K4: s4' = 0.5*(s4 + W4 s3 + b4) ----------------
template <int MODE>
__global__ void __launch_bounds__(256) k4_kernel(int cur, const float* __restrict__ b4) {
    __shared__ ull ws[448 * 8];  // 28.7 KB duplicated
    const int tid = threadIdx.x;
    const int j0 = blockIdx.y * 8;
    const int bp = blockIdx.x * 256 + tid;
    const ull* __restrict__ S3 = (const ull*)g_S3[cur];

    ull acc[8];
#pragma unroll
    for (int r = 0; r < 8; r++) acc[r] = 0ull;

    for (int k0 = 0; k0 < 3136; k0 += 448) {
        __syncthreads();
        for (int i = tid; i < 448; i += 256) {
            const float* src = &g_w4t[(k0 + i) * 256 + j0];
            ull* dst = &ws[i * 8];
#pragma unroll
            for (int r = 0; r < 8; r++) dst[r] = pk(src[r]);
        }
        __syncthreads();
#pragma unroll 4
        for (int kk = 0; kk < 448; kk++) {
            ull sv = S3[(k0 + kk) * PB + bp];
            const ull* wp = &ws[kk * 8];
#pragma unroll
            for (int r = 0; r < 8; r++) acc[r] = fma2(sv, wp[r], acc[r]);
        }
    }

    const ull* __restrict__ S4i = (const ull*)g_S4[cur];
    ull* __restrict__ outp = (ull*)g_S4[cur ^ 1];
    const ull half = pk(0.5f);
#pragma unroll
    for (int r = 0; r < 8; r++) {
        int ii = (j0 + r) * PB + bp;
        ull bias = pk(b4[j0 + r]);
        if (MODE == 0) outp[ii] = mul2(add2(add2(S4i[ii], acc[r]), bias), half);
        else           outp[ii] = add2(acc[r], bias);
    }
}

// ---------------- energy readout ----------------
__global__ void energy_zero(float* __restrict__ out) {
    int b = blockIdx.x * 256 + threadIdx.x;
    out[b] = 0.f;
}

__global__ void energy_partial(const float* __restrict__ vb, int fin,
                               float* __restrict__ out) {
    const int b = blockIdx.x * 256 + threadIdx.x;
    const int s = blockIdx.y;  // 0..7
    const float* __restrict__ S1 = g_S1[fin];
    const float* __restrict__ S2 = g_S2[fin];
    const float* __restrict__ S3 = g_S3[fin];
    const float* __restrict__ S4 = g_S4[fin];
    const float* __restrict__ F2 = g_S2[fin ^ 1];
    const float* __restrict__ F3 = g_S3[fin ^ 1];
    const float* __restrict__ F4 = g_S4[fin ^ 1];

    double e = 0.0;
    if (s == 0) {
        for (int p = 0; p < 784; p++) {
            float xv = g_XT[p * BB + b];
            float term = 0.5f * xv * xv - vb[p] * xv;
            e += (double)term;
        }
        for (int i = 0; i < 256; i++) {
            float sv = S4[i * BB + b];
            float term = 0.5f * sv * sv - sv * F4[i * BB + b];
            e += (double)term;
        }
    }
    {
        int i0 = s * 784;
        for (int i = i0; i < i0 + 784; i++) {
            float sv = S1[i * BB + b];
            float term = 0.5f * sv * sv - sv * g_D1[i * BB + b];
            e += (double)term;
        }
    }
    if (s < 4) {
        int i0 = s * 784;
        for (int i = i0; i < i0 + 784; i++) {
            float sv = S2[i * BB + b];
            float term = 0.5f * sv * sv - sv * F2[i * BB + b];
            e += (double)term;
        }
    } else {
        int i0 = (s - 4) * 784;
        for (int i = i0; i < i0 + 784; i++) {
            float sv = S3[i * BB + b];
            float term = 0.5f * sv * sv - sv * F3[i * BB + b];
            e += (double)term;
        }
    }
    atomicAdd(&out[b], (float)e);
}

// ---------------- launcher ----------------
extern "C" void kernel_launch(void* const* d_in, const int* in_sizes, int n_in,
                              void* d_out, int out_size) {
    const float* x  = (const float*)d_in[0];
    const float* vb = (const float*)d_in[1];
    const float* w1 = (const float*)d_in[2];
    const float* b1 = (const float*)d_in[3];
    const float* w2 = (const float*)d_in[4];
    const float* b2 = (const float*)d_in[5];
    const float* w3 = (const float*)d_in[6];
    const float* b3 = (const float*)d_in[7];
    const float* w4 = (const float*)d_in[8];
    const float* b4 = (const float*)d_in[9];
    float* out = (float*)d_out;

    zero_state<<<2048, 256>>>();
    transpose_x<<<dim3(25, 128), dim3(32, 8)>>>(x);
    prep_weights<<<1024, 256>>>(w2, w3, w4);
    compute_d1<<<dim3(16, 196, 32), 256>>>(w1, b1);

    int cur = 0;
    for (int t = 0; t < 50; t++) {
        k1_update<<<dim3(8, 196, 4), 256>>>(cur);
        k2_kernel<0><<<dim3(8, 49, 8), 256>>>(cur, b2);
        k3_kernel<0><<<dim3(8, 49, 8), 256>>>(cur, b3);
        k4_kernel<0><<<dim3(8, 32, 1), 256>>>(cur, b4);
        cur ^= 1;
    }

    // forward-only passes at the fixed point into the free ping-pong buffers
    k2_kernel<1><<<dim3(8, 49, 8), 256>>>(cur, b2);
    k3_kernel<1><<<dim3(8, 49, 8), 256>>>(cur, b3);
    k4_kernel<1><<<dim3(8, 32, 1), 256>>>(cur, b4);

    energy_zero<<<16, 256>>>(out);
    energy_partial<<<dim3(16, 8), 256>>>(vb, cur, out);
}

// round 8
// speedup vs baseline: 1.8417x; 1.5173x over previous
#include <cuda_runtime.h>

#define BB 4096
#define PB 2048   // f32x2 pairs per row (BB/2)

constexpr int S1N = 32 * 14 * 14;   // 6272
constexpr int S2N = 64 * 7 * 7;     // 3136
constexpr int S3N = 64 * 7 * 7;     // 3136
constexpr int S4N = 256;

typedef unsigned long long ull;

// ---------------- packed f32x2 helpers ----------------
__device__ __forceinline__ ull fma2(ull a, ull b, ull c) {
    ull d; asm("fma.rn.f32x2 %0, %1, %2, %3;" : "=l"(d) : "l"(a), "l"(b), "l"(c)); return d;
}
__device__ __forceinline__ ull add2(ull a, ull b) {
    ull d; asm("add.rn.f32x2 %0, %1, %2;" : "=l"(d) : "l"(a), "l"(b)); return d;
}
__device__ __forceinline__ ull mul2(ull a, ull b) {
    ull d; asm("mul.rn.f32x2 %0, %1, %2;" : "=l"(d) : "l"(a), "l"(b)); return d;
}
__device__ __forceinline__ ull pk(float x) {
    ull d; unsigned u = __float_as_uint(x);
    asm("mov.b64 %0, {%1, %1};" : "=l"(d) : "r"(u)); return d;
}
__device__ __forceinline__ ulonglong2 ld2(const ull* p) {
    return *reinterpret_cast<const ulonglong2*>(p);
}
__device__ __forceinline__ void st2(ull* p, ulonglong2 v) {
    *reinterpret_cast<ulonglong2*>(p) = v;
}

// ---------------- scratch (device globals; allocation-free) ----------------
__device__ float g_S1[2][S1N * BB];
__device__ float g_S2[2][S2N * BB];
__device__ float g_S3[2][S3N * BB];
__device__ float g_S4[2][S4N * BB];
__device__ float g_D1[S1N * BB];        // conv1(x)+b1, batch-minor
__device__ float g_XT[784 * BB];        // x transposed to [pixel][batch]
__device__ float g_w2a[64 * 9 * 32];    // [o][t][c]
__device__ float g_w2b[32 * 9 * 64];    // [c][t][o]
__device__ float g_w3a[64 * 9 * 64];    // [o][t][m]
__device__ float g_w3b[64 * 9 * 64];    // [m][t][o]
__device__ float g_w4t[3136 * 256];     // [k][j]
__device__ float g_w4r[49 * 256 * 64];  // [pos][j][c]

// ---------------- init / prep ----------------
__global__ void zero_state() {
    int stride = gridDim.x * blockDim.x;
    for (int i = blockIdx.x * blockDim.x + threadIdx.x; i < S1N * BB; i += stride) {
        g_S1[0][i] = 0.f;
        if (i < S2N * BB) { g_S2[0][i] = 0.f; g_S3[0][i] = 0.f; }
        if (i < S4N * BB) { g_S4[0][i] = 0.f; }
    }
}

__global__ void transpose_x(const float* __restrict__ x) {
    __shared__ float tile[32][33];
    int p0 = blockIdx.x * 32, b0 = blockIdx.y * 32;
    int tx = threadIdx.x, ty = threadIdx.y;
    for (int i = ty; i < 32; i += 8) {
        int p = p0 + tx;
        tile[i][tx] = (p < 784) ? x[(b0 + i) * 784 + p] : 0.f;
    }
    __syncthreads();
    for (int i = ty; i < 32; i += 8) {
        int p = p0 + i;
        if (p < 784) g_XT[p * BB + b0 + tx] = tile[tx][i];
    }
}

__global__ void prep_weights(const float* __restrict__ w2,
                             const float* __restrict__ w3,
                             const float* __restrict__ w4) {
    int stride = gridDim.x * blockDim.x;
    for (int idx = blockIdx.x * blockDim.x + threadIdx.x; idx < 802816; idx += stride) {
        if (idx < 18432) {  // w2: [o=64][c=32][t=9]
            int o = idx / 288, r = idx % 288, c = r / 9, t = r % 9;
            float v = w2[idx];
            g_w2a[(o * 9 + t) * 32 + c] = v;
            g_w2b[(c * 9 + t) * 64 + o] = v;
        }
        if (idx < 36864) {  // w3: [m=64][o=64][t=9]
            int m = idx / 576, r = idx % 576, o = r / 9, t = r % 9;
            float v = w3[idx];
            g_w3a[(o * 9 + t) * 64 + m] = v;
            g_w3b[(m * 9 + t) * 64 + o] = v;
        }
        {   // w4: [j=256][k=3136]
            int j = idx / 3136, k = idx % 3136;
            float v = w4[idx];
            g_w4t[k * 256 + j] = v;
            int c = k / 49, pos = k % 49;
            g_w4r[(pos * 256 + j) * 64 + c] = v;
        }
    }
}

__global__ void compute_d1(const float* __restrict__ w1, const float* __restrict__ b1) {
    int b = blockIdx.x * 256 + threadIdx.x;
    int pos = blockIdx.y;
    int u = pos / 14, v = pos % 14;
    int c = blockIdx.z;
    float acc = b1[c];
#pragma unroll
    for (int di = 0; di < 3; di++) {
        int h = 2 * u + di - 1;
        if (h < 0 || h >= 28) continue;
#pragma unroll
        for (int dj = 0; dj < 3; dj++) {
            int w = 2 * v + dj - 1;
            if (w < 0 || w >= 28) continue;
            acc = fmaf(w1[c * 9 + di * 3 + dj], g_XT[(h * 28 + w) * BB + b], acc);
        }
    }
    g_D1[(c * 196 + pos) * BB + b] = acc;
}

// ============================================================================
// Fused relaxation step. One launch per step; block-range role dispatch.
// Each thread covers 4 samples (2 ulls via ulonglong2 / LDG.128).
// STATIC shared memory only (46.1 KB): 576*8 ull (duplicated) + 288*8 float.
// Role layout (grid.x = 6400):
//   [0,    128): k4  (s4' update; memory-latency-bound — scheduled first)
//   [128, 3264): k1  (s1' update)  4*196*4 blocks
//   [3264,4832): k2  (s2' update)  4*49*8  blocks
//   [4832,6400): k3  (s3' update)  4*49*8  blocks
// ============================================================================
#define K4_BASE 0
#define K1_BASE 128
#define K2_BASE 3264
#define K3_BASE 4832
#define STEP_GRID 6400

__global__ void __launch_bounds__(256) step_kernel(int cur,
                                                   const float* __restrict__ b2,
                                                   const float* __restrict__ b3,
                                                   const float* __restrict__ b4) {
    __shared__ ull   smw[576 * 8];   // 36864 B: big duplicated weight slice
    __shared__ float smf[288 * 8];   //  9216 B: small plain-float weight slice
    const int tid = threadIdx.x;
    const int bx = blockIdx.x;
    const ull half = pk(0.5f);

    if (bx < K1_BASE) {
        // ---------------- K4: s4' = 0.5*(s4 + W4 s3 + b4) ----------------
        int idx = bx - K4_BASE;
        const int bb = idx & 3;
        const int j0 = (idx >> 2) * 8;
        const int u = bb * 512 + 2 * tid;
        const ull* __restrict__ S3 = (const ull*)g_S3[cur];
        ull* ws = smw;  // uses 448*8 ulls

        ull ax[8], ay[8];
#pragma unroll
        for (int r = 0; r < 8; r++) { ax[r] = 0ull; ay[r] = 0ull; }

        for (int k0 = 0; k0 < 3136; k0 += 448) {
            __syncthreads();
            for (int i = tid; i < 448; i += 256) {
                const float* src = &g_w4t[(k0 + i) * 256 + j0];
                ull* dst = &ws[i * 8];
#pragma unroll
                for (int r = 0; r < 8; r++) dst[r] = pk(src[r]);
            }
            __syncthreads();
#pragma unroll 4
            for (int kk = 0; kk < 448; kk++) {
                ulonglong2 sv = ld2(S3 + (k0 + kk) * PB + u);
                const ull* wp = &ws[kk * 8];
#pragma unroll
                for (int r = 0; r < 8; r++) {
                    ax[r] = fma2(sv.x, wp[r], ax[r]);
                    ay[r] = fma2(sv.y, wp[r], ay[r]);
                }
            }
        }

        const ull* __restrict__ S4i = (const ull*)g_S4[cur];
        ull* __restrict__ outp = (ull*)g_S4[cur ^ 1];
#pragma unroll
        for (int r = 0; r < 8; r++) {
            int ii = (j0 + r) * PB + u;
            ull bias = pk(b4[j0 + r]);
            ulonglong2 si = ld2(S4i + ii);
            ulonglong2 o;
            o.x = mul2(add2(add2(si.x, ax[r]), bias), half);
            o.y = mul2(add2(add2(si.y, ay[r]), bias), half);
            st2(outp + ii, o);
        }
    } else if (bx < K2_BASE) {
        // ---------------- K1: s1' = 0.5*(s1 + d1 + tconv2(s2)) ----------------
        int idx = bx - K1_BASE;
        const int bb = idx & 3; idx >>= 2;
        const int pos = idx % 196;
        const int c0 = (idx / 196) * 8;
        const int u_ = bb * 512 + 2 * tid;
        ull* ws = smw;  // 576*8 ulls

        for (int i = tid; i < 576; i += 256) {
            const float* src = &g_w2a[i * 32 + c0];
            ull* dst = &ws[i * 8];
#pragma unroll
            for (int r = 0; r < 8; r++) dst[r] = pk(src[r]);
        }
        __syncthreads();

        const int uu = pos / 14, vv = pos % 14;
        int p0, p1, wu0, wu1; bool vu0, vu1;
        if (uu & 1) { p0 = (uu + 1) >> 1; wu0 = 0; vu0 = (p0 < 7);
                      p1 = (uu - 1) >> 1; wu1 = 2; vu1 = true; }
        else        { p0 = uu >> 1;       wu0 = 1; vu0 = true;
                      p1 = 0;             wu1 = 0; vu1 = false; }
        int q0, q1, wv0, wv1; bool vv0, vv1;
        if (vv & 1) { q0 = (vv + 1) >> 1; wv0 = 0; vv0 = (q0 < 7);
                      q1 = (vv - 1) >> 1; wv1 = 2; vv1 = true; }
        else        { q0 = vv >> 1;       wv0 = 1; vv0 = true;
                      q1 = 0;             wv1 = 0; vv1 = false; }

        const int off00 = (p0 * 7 + q0) * PB, wa00 = (wu0 * 3 + wv0) * 8; const bool ok00 = vu0 && vv0;
        const int off01 = (p0 * 7 + q1) * PB, wa01 = (wu0 * 3 + wv1) * 8; const bool ok01 = vu0 && vv1;
        const int off10 = (p1 * 7 + q0) * PB, wa10 = (wu1 * 3 + wv0) * 8; const bool ok10 = vu1 && vv0;
        const int off11 = (p1 * 7 + q1) * PB, wa11 = (wu1 * 3 + wv1) * 8; const bool ok11 = vu1 && vv1;

        const ull* __restrict__ S2 = (const ull*)g_S2[cur];
        ull ax[8], ay[8];
#pragma unroll
        for (int r = 0; r < 8; r++) { ax[r] = 0ull; ay[r] = 0ull; }

#pragma unroll 2
        for (int o = 0; o < 64; o++) {
            const ull* base = S2 + o * 49 * PB + u_;
            const ull* wb = ws + o * 72;
            if (ok00) { ulonglong2 sv = ld2(base + off00); const ull* wp = wb + wa00;
#pragma unroll
                for (int r = 0; r < 8; r++) { ax[r] = fma2(sv.x, wp[r], ax[r]); ay[r] = fma2(sv.y, wp[r], ay[r]); } }
            if (ok01) { ulonglong2 sv = ld2(base + off01); const ull* wp = wb + wa01;
#pragma unroll
                for (int r = 0; r < 8; r++) { ax[r] = fma2(sv.x, wp[r], ax[r]); ay[r] = fma2(sv.y, wp[r], ay[r]); } }
            if (ok10) { ulonglong2 sv = ld2(base + off10); const ull* wp = wb + wa10;
#pragma unroll
                for (int r = 0; r < 8; r++) { ax[r] = fma2(sv.x, wp[r], ax[r]); ay[r] = fma2(sv.y, wp[r], ay[r]); } }
            if (ok11) { ulonglong2 sv = ld2(base + off11); const ull* wp = wb + wa11;
#pragma unroll
                for (int r = 0; r < 8; r++) { ax[r] = fma2(sv.x, wp[r], ax[r]); ay[r] = fma2(sv.y, wp[r], ay[r]); } }
        }

        const ull* __restrict__ S1i = (const ull*)g_S1[cur];
        const ull* __restrict__ D1 = (const ull*)g_D1;
        ull* __restrict__ S1o = (ull*)g_S1[cur ^ 1];
        const int oidx = (c0 * 196 + pos) * PB + u_;
#pragma unroll
        for (int r = 0; r < 8; r++) {
            int ii = oidx + r * (196 * PB);
            ulonglong2 si = ld2(S1i + ii), d1 = ld2(D1 + ii);
            ulonglong2 o;
            o.x = mul2(add2(add2(si.x, d1.x), ax[r]), half);
            o.y = mul2(add2(add2(si.y, d1.y), ay[r]), half);
            st2(S1o + ii, o);
        }
    } else if (bx < K3_BASE) {
        // ---------------- K2: s2' = 0.5*(s2 + conv2(s1)+b2 + tconv3(s3)) ----------------
        int idx = bx - K2_BASE;
        const int bb = idx & 3; idx >>= 2;
        const int pos = idx % 49;
        const int o0 = (idx / 49) * 8;
        const int u_ = bb * 512 + 2 * tid;
        float* ws2 = smf;  // 288*8 floats (conv2 weights, plain)
        ull*   ws3 = smw;  // 576*8 ulls (tconv3 weights, duplicated)

        for (int i = tid; i < 288; i += 256) {
            const float* src = &g_w2b[i * 64 + o0];
            float* dst = &ws2[i * 8];
#pragma unroll
            for (int r = 0; r < 8; r++) dst[r] = src[r];
        }
        for (int i = tid; i < 576; i += 256) {
            const float* src = &g_w3b[i * 64 + o0];
            ull* dst = &ws3[i * 8];
#pragma unroll
            for (int r = 0; r < 8; r++) dst[r] = pk(src[r]);
        }
        __syncthreads();

        const int p = pos / 7, q = pos % 7;
        ull ax[8], ay[8];
#pragma unroll
        for (int r = 0; r < 8; r++) { ax[r] = 0ull; ay[r] = 0ull; }

        // conv2(s1): stride 2
        {
            int off[9]; bool ok[9];
#pragma unroll
            for (int di = 0; di < 3; di++)
#pragma unroll
                for (int dj = 0; dj < 3; dj++) {
                    int h = 2 * p + di - 1, w = 2 * q + dj - 1;
                    ok[di * 3 + dj] = (h >= 0) && (w >= 0);
                    off[di * 3 + dj] = (h * 14 + w) * PB;
                }
            const ull* __restrict__ S1 = (const ull*)g_S1[cur];
#pragma unroll 2
            for (int c = 0; c < 32; c++) {
                const ull* base = S1 + c * 196 * PB + u_;
                const float* wb = ws2 + c * 72;
#pragma unroll
                for (int t = 0; t < 9; t++) {
                    if (ok[t]) {
                        ulonglong2 sv = ld2(base + off[t]);
                        const float* wp = wb + t * 8;
#pragma unroll
                        for (int r = 0; r < 8; r++) {
                            ull w2p = pk(wp[r]);
                            ax[r] = fma2(sv.x, w2p, ax[r]);
                            ay[r] = fma2(sv.y, w2p, ay[r]);
                        }
                    }
                }
            }
        }
        // tconv3(s3): stride 1, flipped
        {
            int off[9]; bool ok[9];
#pragma unroll
            for (int di = 0; di < 3; di++)
#pragma unroll
                for (int dj = 0; dj < 3; dj++) {
                    int rr = p + 1 - di, cc = q + 1 - dj;
                    ok[di * 3 + dj] = (rr >= 0) && (rr < 7) && (cc >= 0) && (cc < 7);
                    off[di * 3 + dj] = (rr * 7 + cc) * PB;
                }
            const ull* __restrict__ S3 = (const ull*)g_S3[cur];
#pragma unroll 2
            for (int m = 0; m < 64; m++) {
                const ull* base = S3 + m * 49 * PB + u_;
                const ull* wb = ws3 + m * 72;
#pragma unroll
                for (int t = 0; t < 9; t++) {
                    if (ok[t]) {
                        ulonglong2 sv = ld2(base + off[t]);
                        const ull* wp = wb + t * 8;
#pragma unroll
                        for (int r = 0; r < 8; r++) { ax[r] = fma2(sv.x, wp[r], ax[r]); ay[r] = fma2(sv.y, wp[r], ay[r]); }
                    }
                }
            }
        }

        const ull* __restrict__ S2i = (const ull*)g_S2[cur];
        ull* __restrict__ outp = (ull*)g_S2[cur ^ 1];
        const int oidx = (o0 * 49 + pos) * PB + u_;
#pragma unroll
        for (int r = 0; r < 8; r++) {
            int ii = oidx + r * (49 * PB);
            ull bias = pk(b2[o0 + r]);
            ulonglong2 si = ld2(S2i + ii);
            ulonglong2 o;
            o.x = mul2(add2(add2(si.x, ax[r]), bias), half);
            o.y = mul2(add2(add2(si.y, ay[r]), bias), half);
            st2(outp + ii, o);
        }
    } else {
        // ---------------- K3: s3' = 0.5*(s3 + conv3(s2)+b3 + W4^T s4) ----------------
        int idx = bx - K3_BASE;
        const int bb = idx & 3; idx >>= 2;
        const int pos = idx % 49;
        const int c0 = (idx / 49) * 8;
        const int u_ = bb * 512 + 2 * tid;
        ull*   ws3 = smw;  // 576*8 ulls (conv3 weights, duplicated)
        float* ws4 = smf;  // 256*8 floats (W4 slice, plain)

        for (int i = tid; i < 576; i += 256) {
            const float* src = &g_w3a[i * 64 + c0];
            ull* dst = &ws3[i * 8];
#pragma unroll
            for (int r = 0; r < 8; r++) dst[r] = pk(src[r]);
        }
        for (int j = tid; j < 256; j += 256) {
            const float* src = &g_w4r[(pos * 256 + j) * 64 + c0];
            float* dst = &ws4[j * 8];
#pragma unroll
            for (int r = 0; r < 8; r++) dst[r] = src[r];
        }
        __syncthreads();

        const int p = pos / 7, q = pos % 7;
        ull ax[8], ay[8];
#pragma unroll
        for (int r = 0; r < 8; r++) { ax[r] = 0ull; ay[r] = 0ull; }

        // conv3(s2): stride 1
        {
            int off[9]; bool ok[9];
#pragma unroll
            for (int di = 0; di < 3; di++)
#pragma unroll
                for (int dj = 0; dj < 3; dj++) {
                    int h = p + di - 1, w = q + dj - 1;
                    ok[di * 3 + dj] = (h >= 0) && (h < 7) && (w >= 0) && (w < 7);
                    off[di * 3 + dj] = (h * 7 + w) * PB;
                }
            const ull* __restrict__ S2 = (const ull*)g_S2[cur];
#pragma unroll 2
            for (int o = 0; o < 64; o++) {
                const ull* base = S2 + o * 49 * PB + u_;
                const ull* wb = ws3 + o * 72;
#pragma unroll
                for (int t = 0; t < 9; t++) {
                    if (ok[t]) {
                        ulonglong2 sv = ld2(base + off[t]);
                        const ull* wp = wb + t * 8;
#pragma unroll
                        for (int r = 0; r < 8; r++) { ax[r] = fma2(sv.x, wp[r], ax[r]); ay[r] = fma2(sv.y, wp[r], ay[r]); }
                    }
                }
            }
        }
        // W4^T s4
        {
            const ull* __restrict__ S4 = (const ull*)g_S4[cur];
#pragma unroll 2
            for (int j = 0; j < 256; j++) {
                ulonglong2 sv = ld2(S4 + j * PB + u_);
                const float* wp = &ws4[j * 8];
#pragma unroll
                for (int r = 0; r < 8; r++) {
                    ull w4p = pk(wp[r]);
                    ax[r] = fma2(sv.x, w4p, ax[r]);
                    ay[r] = fma2(sv.y, w4p, ay[r]);
                }
            }
        }

        const ull* __restrict__ S3i = (const ull*)g_S3[cur];
        ull* __restrict__ outp = (ull*)g_S3[cur ^ 1];
        const int oidx = (c0 * 49 + pos) * PB + u_;
#pragma unroll
        for (int r = 0; r < 8; r++) {
            int ii = oidx + r * (49 * PB);
            ull bias = pk(b3[c0 + r]);
            ulonglong2 si = ld2(S3i + ii);
            ulonglong2 o;
            o.x = mul2(add2(add2(si.x, ax[r]), bias), half);
            o.y = mul2(add2(add2(si.y, ay[r]), bias), half);
            st2(outp + ii, o);
        }
    }
}

// ============================================================================
// Forward-only kernels for energy readout (run once)
// ============================================================================
__global__ void __launch_bounds__(256) fwd2_kernel(int cur, const float* __restrict__ b2) {
    __shared__ float ws2[288 * 8];
    const int tid = threadIdx.x;
    const int o0 = blockIdx.z * 8;
    for (int i = tid; i < 288; i += 256) {
        const float* src = &g_w2b[i * 64 + o0];
        float* dst = &ws2[i * 8];
#pragma unroll
        for (int r = 0; r < 8; r++) dst[r] = src[r];
    }
    __syncthreads();

    const int bp = blockIdx.x * 256 + tid;
    const int pos = blockIdx.y;
    const int p = pos / 7, q = pos % 7;

    ull acc[8];
#pragma unroll
    for (int r = 0; r < 8; r++) acc[r] = 0ull;

    int off[9]; bool ok[9];
#pragma unroll
    for (int di = 0; di < 3; di++)
#pragma unroll
        for (int dj = 0; dj < 3; dj++) {
            int h = 2 * p + di - 1, w = 2 * q + dj - 1;
            ok[di * 3 + dj] = (h >= 0) && (w >= 0);
            off[di * 3 + dj] = (h * 14 + w) * PB;
        }
    const ull* __restrict__ S1 = (const ull*)g_S1[cur];
#pragma unroll 2
    for (int c = 0; c < 32; c++) {
        const ull* base = S1 + c * 196 * PB + bp;
        const float* wb = ws2 + c * 72;
#pragma unroll
        for (int t = 0; t < 9; t++) {
            if (ok[t]) {
                ull sv = base[off[t]];
                const float* wp = wb + t * 8;
#pragma unroll
                for (int r = 0; r < 8; r++) acc[r] = fma2(sv, pk(wp[r]), acc[r]);
            }
        }
    }

    ull* __restrict__ outp = (ull*)g_S2[cur ^ 1];
    const int oidx = (o0 * 49 + pos) * PB + bp;
#pragma unroll
    for (int r = 0; r < 8; r++) outp[oidx + r * (49 * PB)] = add2(acc[r], pk(b2[o0 + r]));
}

__global__ void __launch_bounds__(256) fwd3_kernel(int cur, const float* __restrict__ b3) {
    __shared__ ull ws3[576 * 8];
    const int tid = threadIdx.x;
    const int c0 = blockIdx.z * 8;
    const int pos = blockIdx.y;
    for (int i = tid; i < 576; i += 256) {
        const float* src = &g_w3a[i * 64 + c0];
        ull* dst = &ws3[i * 8];
#pragma unroll
        for (int r = 0; r < 8; r++) dst[r] = pk(src[r]);
    }
    __syncthreads();

    const int bp = blockIdx.x * 256 + tid;
    const int p = pos / 7, q = pos % 7;

    ull acc[8];
#pragma unroll
    for (int r = 0; r < 8; r++) acc[r] = 0ull;

    int off[9]; bool ok[9];
#pragma unroll
    for (int di = 0; di < 3; di++)
#pragma unroll
        for (int dj = 0; dj < 3; dj++) {
            int h = p + di - 1, w = q + dj - 1;
            ok[di * 3 + dj] = (h >= 0) && (h < 7) && (w >= 0) && (w < 7);
            off[di * 3 + dj] = (h * 7 + w) * PB;
        }
    const ull* __restrict__ S2 = (const ull*)g_S2[cur];
#pragma unroll 2
    for (int o = 0; o < 64; o++) {
        const ull* base = S2 + o * 49 * PB + bp;
        const ull* wb = ws3 + o * 72;
#pragma unroll
        for (int t = 0; t < 9; t++) {
            if (ok[t]) {
                ull sv = base[off[t]];
                const ull* wp = wb + t * 8;
#pragma unroll
                for (int r = 0; r < 8; r++) acc[r] = fma2(sv, wp[r], acc[r]);
            }
        }
    }

    ull* __restrict__ outp = (ull*)g_S3[cur ^ 1];
    const int oidx = (c0 * 49 + pos) * PB + bp;
#pragma unroll
    for (int r = 0; r < 8; r++) outp[oidx + r * (49 * PB)] = add2(acc[r], pk(b3[c0 + r]));
}

__global__ void __launch_bounds__(256) fwd4_kernel(int cur, const float* __restrict__ b4) {
    __shared__ ull ws[448 * 8];
    const int tid = threadIdx.x;
    const int j0 = blockIdx.y * 8;
    const int bp = blockIdx.x * 256 + tid;
    const ull* __restrict__ S3 = (const ull*)g_S3[cur];

    ull acc[8];
#pragma unroll
    for (int r = 0; r < 8; r++) acc[r] = 0ull;

    for (int k0 = 0; k0 < 3136; k0 += 448) {
        __syncthreads();
        for (int i = tid; i < 448; i += 256) {
            const float* src = &g_w4t[(k0 + i) * 256 + j0];
            ull* dst = &ws[i * 8];
#pragma unroll
            for (int r = 0; r < 8; r++) dst[r] = pk(src[r]);
        }
        __syncthreads();
#pragma unroll 4
        for (int kk = 0; kk < 448; kk++) {
            ull sv = S3[(k0 + kk) * PB + bp];
            const ull* wp = &ws[kk * 8];
#pragma unroll
            for (int r = 0; r < 8; r++) acc[r] = fma2(sv, wp[r], acc[r]);
        }
    }

    ull* __restrict__ outp = (ull*)g_S4[cur ^ 1];
#pragma unroll
    for (int r = 0; r < 8; r++) outp[(j0 + r) * PB + bp] = add2(acc[r], pk(b4[j0 + r]));
}

// ---------------- energy readout ----------------
__global__ void energy_zero(float* __restrict__ out) {
    int b = blockIdx.x * 256 + threadIdx.x;
    out[b] = 0.f;
}

__global__ void energy_partial(const float* __restrict__ vb, int fin,
                               float* __restrict__ out) {
    const int b = blockIdx.x * 256 + threadIdx.x;
    const int s = blockIdx.y;  // 0..7
    const float* __restrict__ S1 = g_S1[fin];
    const float* __restrict__ S2 = g_S2[fin];
    const float* __restrict__ S3 = g_S3[fin];
    const float* __restrict__ S4 = g_S4[fin];
    const float* __restrict__ F2 = g_S2[fin ^ 1];
    const float* __restrict__ F3 = g_S3[fin ^ 1];
    const float* __restrict__ F4 = g_S4[fin ^ 1];

    double e = 0.0;
    if (s == 0) {
        for (int p = 0; p < 784; p++) {
            float xv = g_XT[p * BB + b];
            float term = 0.5f * xv * xv - vb[p] * xv;
            e += (double)term;
        }
        for (int i = 0; i < 256; i++) {
            float sv = S4[i * BB + b];
            float term = 0.5f * sv * sv - sv * F4[i * BB + b];
            e += (double)term;
        }
    }
    {
        int i0 = s * 784;
        for (int i = i0; i < i0 + 784; i++) {
            float sv = S1[i * BB + b];
            float term = 0.5f * sv * sv - sv * g_D1[i * BB + b];
            e += (double)term;
        }
    }
    if (s < 4) {
        int i0 = s * 784;
        for (int i = i0; i < i0 + 784; i++) {
            float sv = S2[i * BB + b];
            float term = 0.5f * sv * sv - sv * F2[i * BB + b];
            e += (double)term;
        }
    } else {
        int i0 = (s - 4) * 784;
        for (int i = i0; i < i0 + 784; i++) {
            float sv = S3[i * BB + b];
            float term = 0.5f * sv * sv - sv * F3[i * BB + b];
            e += (double)term;
        }
    }
    atomicAdd(&out[b], (float)e);
}

// ---------------- launcher ----------------
extern "C" void kernel_launch(void* const* d_in, const int* in_sizes, int n_in,
                              void* d_out, int out_size) {
    const float* x  = (const float*)d_in[0];
    const float* vb = (const float*)d_in[1];
    const float* w1 = (const float*)d_in[2];
    const float* b1 = (const float*)d_in[3];
    const float* w2 = (const float*)d_in[4];
    const float* b2 = (const float*)d_in[5];
    const float* w3 = (const float*)d_in[6];
    const float* b3 = (const float*)d_in[7];
    const float* w4 = (const float*)d_in[8];
    const float* b4 = (const float*)d_in[9];
    float* out = (float*)d_out;

    zero_state<<<2048, 256>>>();
    transpose_x<<<dim3(25, 128), dim3(32, 8)>>>(x);
    prep_weights<<<1024, 256>>>(w2, w3, w4);
    compute_d1<<<dim3(16, 196, 32), 256>>>(w1, b1);

    int cur = 0;
    for (int t = 0; t < 50; t++) {
        step_kernel<<<STEP_GRID, 256>>>(cur, b2, b3, b4);
        cur ^= 1;
    }

    // forward-only passes at the fixed point into the free ping-pong buffers
    fwd2_kernel<<<dim3(8, 49, 8), 256>>>(cur, b2);
    fwd3_kernel<<<dim3(8, 49, 8), 256>>>(cur, b3);
    fwd4_kernel<<<dim3(8, 32, 1), 256>>>(cur, b4);

    energy_zero<<<16, 256>>>(out);
    energy_partial<<<dim3(16, 8), 256>>>(vb, cur, out);
}

// round 10
// speedup vs baseline: 1.9865x; 1.0786x over previous
#include <cuda_runtime.h>

#define BB 4096
#define PB 2048   // f32x2 pairs per row (BB/2)

// padded spatial layouts: S1 16x16 (14x14 interior), S2/S3 9x9 (7x7 interior)
constexpr int S1R = 32 * 256;   // 8192 rows
constexpr int S2R = 64 * 81;    // 5184 rows
constexpr int S3R = 64 * 81;
constexpr int S4N = 256;

typedef unsigned long long ull;

// ---------------- packed f32x2 helpers ----------------
__device__ __forceinline__ ull fma2(ull a, ull b, ull c) {
    ull d; asm("fma.rn.f32x2 %0, %1, %2, %3;" : "=l"(d) : "l"(a), "l"(b), "l"(c)); return d;
}
__device__ __forceinline__ ull add2(ull a, ull b) {
    ull d; asm("add.rn.f32x2 %0, %1, %2;" : "=l"(d) : "l"(a), "l"(b)); return d;
}
__device__ __forceinline__ ull mul2(ull a, ull b) {
    ull d; asm("mul.rn.f32x2 %0, %1, %2;" : "=l"(d) : "l"(a), "l"(b)); return d;
}
__device__ __forceinline__ ull pk(float x) {
    ull d; unsigned u = __float_as_uint(x);
    asm("mov.b64 %0, {%1, %1};" : "=l"(d) : "r"(u)); return d;
}
__device__ __forceinline__ ulonglong2 ld2(const ull* p) {
    return *reinterpret_cast<const ulonglong2*>(p);
}
__device__ __forceinline__ void st2(ull* p, ulonglong2 v) {
    *reinterpret_cast<ulonglong2*>(p) = v;
}

// ---------------- scratch (device globals; allocation-free) ----------------
__device__ float g_S1[2][S1R * BB];     // padded [c][16x16][b]
__device__ float g_S2[2][S2R * BB];     // padded [c][9x9][b]
__device__ float g_S3[2][S3R * BB];
__device__ float g_S4[2][S4N * BB];
__device__ float g_D1[S1R * BB];        // conv1(x)+b1, padded like S1
__device__ float g_XT[784 * BB];        // x transposed [pixel][batch], unpadded
__device__ float g_w2a[64 * 9 * 32];    // [o][t][c]
__device__ float g_w2b[32 * 9 * 64];    // [c][t][o]
__device__ float g_w3a[64 * 9 * 64];    // [o][t][m]
__device__ float g_w3b[64 * 9 * 64];    // [m][t][o]
__device__ float g_w4t[3136 * 256];     // [k][j]
__device__ float g_w4r[49 * 256 * 64];  // [pos][j][c]

// ---------------- init / prep ----------------
__global__ void zero_state() {
    int stride = gridDim.x * blockDim.x;
    float4 z = make_float4(0.f, 0.f, 0.f, 0.f);
    const int n1 = S1R * BB / 4;
    const int n2 = S2R * BB / 4;
    const int n4 = S4N * BB / 4;
    for (int i = blockIdx.x * blockDim.x + threadIdx.x; i < n1; i += stride) {
        reinterpret_cast<float4*>(g_S1[0])[i] = z;
        reinterpret_cast<float4*>(g_S1[1])[i] = z;
        reinterpret_cast<float4*>(g_D1)[i] = z;
        if (i < n2) {
            reinterpret_cast<float4*>(g_S2[0])[i] = z;
            reinterpret_cast<float4*>(g_S2[1])[i] = z;
            reinterpret_cast<float4*>(g_S3[0])[i] = z;
            reinterpret_cast<float4*>(g_S3[1])[i] = z;
        }
        if (i < n4) reinterpret_cast<float4*>(g_S4[0])[i] = z;
    }
}

__global__ void transpose_x(const float* __restrict__ x) {
    __shared__ float tile[32][33];
    int p0 = blockIdx.x * 32, b0 = blockIdx.y * 32;
    int tx = threadIdx.x, ty = threadIdx.y;
    for (int i = ty; i < 32; i += 8) {
        int p = p0 + tx;
        tile[i][tx] = (p < 784) ? x[(b0 + i) * 784 + p] : 0.f;
    }
    __syncthreads();
    for (int i = ty; i < 32; i += 8) {
        int p = p0 + i;
        if (p < 784) g_XT[p * BB + b0 + tx] = tile[tx][i];
    }
}

__global__ void prep_weights(const float* __restrict__ w2,
                             const float* __restrict__ w3,
                             const float* __restrict__ w4) {
    int stride = gridDim.x * blockDim.x;
    for (int idx = blockIdx.x * blockDim.x + threadIdx.x; idx < 802816; idx += stride) {
        if (idx < 18432) {  // w2: [o=64][c=32][t=9]
            int o = idx / 288, r = idx % 288, c = r / 9, t = r % 9;
            float v = w2[idx];
            g_w2a[(o * 9 + t) * 32 + c] = v;
            g_w2b[(c * 9 + t) * 64 + o] = v;
        }
        if (idx < 36864) {  // w3: [m=64][o=64][t=9]
            int m = idx / 576, r = idx % 576, o = r / 9, t = r % 9;
            float v = w3[idx];
            g_w3a[(o * 9 + t) * 64 + m] = v;
            g_w3b[(m * 9 + t) * 64 + o] = v;
        }
        {   // w4: [j=256][k=3136]
            int j = idx / 3136, k = idx % 3136;
            float v = w4[idx];
            g_w4t[k * 256 + j] = v;
            int c = k / 49, pos = k % 49;
            g_w4r[(pos * 256 + j) * 64 + c] = v;
        }
    }
}

__global__ void compute_d1(const float* __restrict__ w1, const float* __restrict__ b1) {
    int b = blockIdx.x * 256 + threadIdx.x;
    int pos = blockIdx.y;
    int u = pos / 14, v = pos % 14;
    int c = blockIdx.z;
    float acc = b1[c];
#pragma unroll
    for (int di = 0; di < 3; di++) {
        int h = 2 * u + di - 1;
        if (h < 0 || h >= 28) continue;
#pragma unroll
        for (int dj = 0; dj < 3; dj++) {
            int w = 2 * v + dj - 1;
            if (w < 0 || w >= 28) continue;
            acc = fmaf(w1[c * 9 + di * 3 + dj], g_XT[(h * 28 + w) * BB + b], acc);
        }
    }
    g_D1[(c * 256 + (u + 1) * 16 + (v + 1)) * BB + b] = acc;
}

// ============================================================================
// Fused relaxation step. One launch per step; block-range role dispatch.
// 4 samples/thread (ulonglong2 / LDG.128). Branchless inner loops via halos.
// Static smem 46.1 KB: 576*8 ull (duplicated) + 288*8 float.
// Role layout (grid.x = 6400):
//   [0,    128): k4   [128, 3264): k1   [3264, 4832): k2   [4832, 6400): k3
// ============================================================================
#define K4_BASE 0
#define K1_BASE 128
#define K2_BASE 3264
#define K3_BASE 4832
#define STEP_GRID 6400

__global__ void __launch_bounds__(256) step_kernel(int cur,
                                                   const float* __restrict__ b2,
                                                   const float* __restrict__ b3,
                                                   const float* __restrict__ b4) {
    __shared__ ull   smw[576 * 8];   // 36864 B
    __shared__ float smf[288 * 8];   //  9216 B
    const int tid = threadIdx.x;
    const int bx = blockIdx.x;
    const ull half = pk(0.5f);

    if (bx < K1_BASE) {
        // ---------------- K4: s4' = 0.5*(s4 + W4 s3 + b4) ----------------
        int idx = bx - K4_BASE;
        const int bb = idx & 3;
        const int j0 = (idx >> 2) * 8;
        const int u = bb * 512 + 2 * tid;
        const ull* __restrict__ S3 = (const ull*)g_S3[cur];
        ull* ws = smw;  // 392*8 ulls per chunk

        ull ax[8], ay[8];
#pragma unroll
        for (int r = 0; r < 8; r++) { ax[r] = 0ull; ay[r] = 0ull; }

        for (int ch = 0; ch < 8; ch++) {           // 8 chunks of 8 channels
            __syncthreads();
            for (int i = tid; i < 392; i += 256) {
                const float* src = &g_w4t[(ch * 392 + i) * 256 + j0];
                ull* dst = &ws[i * 8];
#pragma unroll
                for (int r = 0; r < 8; r++) dst[r] = pk(src[r]);
            }
            __syncthreads();
            for (int cc = 0; cc < 8; cc++) {
                const ull* cb = S3 + ((ch * 8 + cc) * 81) * PB + u;
                const ull* wch = ws + cc * 392;
                int kk = 0;
#pragma unroll
                for (int pp = 1; pp <= 7; pp++) {
#pragma unroll
                    for (int qq = 1; qq <= 7; qq++) {
                        ulonglong2 sv = ld2(cb + (pp * 9 + qq) * PB);
                        const ull* wp = wch + kk * 8; kk++;
#pragma unroll
                        for (int r = 0; r < 8; r++) {
                            ax[r] = fma2(sv.x, wp[r], ax[r]);
                            ay[r] = fma2(sv.y, wp[r], ay[r]);
                        }
                    }
                }
            }
        }

        const ull* __restrict__ S4i = (const ull*)g_S4[cur];
        ull* __restrict__ outp = (ull*)g_S4[cur ^ 1];
#pragma unroll
        for (int r = 0; r < 8; r++) {
            int ii = (j0 + r) * PB + u;
            ull bias = pk(b4[j0 + r]);
            ulonglong2 si = ld2(S4i + ii);
            ulonglong2 o;
            o.x = mul2(add2(add2(si.x, ax[r]), bias), half);
            o.y = mul2(add2(add2(si.y, ay[r]), bias), half);
            st2(outp + ii, o);
        }
    } else if (bx < K2_BASE) {
        // ---------------- K1: s1' = 0.5*(s1 + d1 + tconv2(s2)) ----------------
        int idx = bx - K1_BASE;
        const int bb = idx & 3; idx >>= 2;
        const int pos = idx % 196;
        const int c0 = (idx / 196) * 8;
        const int u_ = bb * 512 + 2 * tid;
        ull* ws = smw;

        for (int i = tid; i < 576; i += 256) {
            const float* src = &g_w2a[i * 32 + c0];
            ull* dst = &ws[i * 8];
#pragma unroll
            for (int r = 0; r < 8; r++) dst[r] = pk(src[r]);
        }
        __syncthreads();

        const int uu = pos / 14, vv = pos % 14;
        // padded S2 row indices; structurally-absent taps -> halo row/col 8 (zeros)
        int p0r, p1r, wu0, wu1;
        if (uu & 1) { p0r = ((uu + 1) >> 1) + 1; wu0 = 0;
                      p1r = ((uu - 1) >> 1) + 1; wu1 = 2; }
        else        { p0r = (uu >> 1) + 1;       wu0 = 1;
                      p1r = 8;                   wu1 = 0; }
        int q0r, q1r, wv0, wv1;
        if (vv & 1) { q0r = ((vv + 1) >> 1) + 1; wv0 = 0;
                      q1r = ((vv - 1) >> 1) + 1; wv1 = 2; }
        else        { q0r = (vv >> 1) + 1;       wv0 = 1;
                      q1r = 8;                   wv1 = 0; }

        const int off00 = (p0r * 9 + q0r) * PB, wa00 = (wu0 * 3 + wv0) * 8;
        const int off01 = (p0r * 9 + q1r) * PB, wa01 = (wu0 * 3 + wv1) * 8;
        const int off10 = (p1r * 9 + q0r) * PB, wa10 = (wu1 * 3 + wv0) * 8;
        const int off11 = (p1r * 9 + q1r) * PB, wa11 = (wu1 * 3 + wv1) * 8;

        const ull* __restrict__ S2 = (const ull*)g_S2[cur];
        ull ax[8], ay[8];
#pragma unroll
        for (int r = 0; r < 8; r++) { ax[r] = 0ull; ay[r] = 0ull; }

#pragma unroll 2
        for (int o = 0; o < 64; o++) {
            const ull* base = S2 + o * 81 * PB + u_;
            const ull* wb = ws + o * 72;
            {   ulonglong2 sv = ld2(base + off00); const ull* wp = wb + wa00;
#pragma unroll
                for (int r = 0; r < 8; r++) { ax[r] = fma2(sv.x, wp[r], ax[r]); ay[r] = fma2(sv.y, wp[r], ay[r]); } }
            {   ulonglong2 sv = ld2(base + off01); const ull* wp = wb + wa01;
#pragma unroll
                for (int r = 0; r < 8; r++) { ax[r] = fma2(sv.x, wp[r], ax[r]); ay[r] = fma2(sv.y, wp[r], ay[r]); } }
            {   ulonglong2 sv = ld2(base + off10); const ull* wp = wb + wa10;
#pragma unroll
                for (int r = 0; r < 8; r++) { ax[r] = fma2(sv.x, wp[r], ax[r]); ay[r] = fma2(sv.y, wp[r], ay[r]); } }
            {   ulonglong2 sv = ld2(base + off11); const ull* wp = wb + wa11;
#pragma unroll
                for (int r = 0; r < 8; r++) { ax[r] = fma2(sv.x, wp[r], ax[r]); ay[r] = fma2(sv.y, wp[r], ay[r]); } }
        }

        const ull* __restrict__ S1i = (const ull*)g_S1[cur];
        const ull* __restrict__ D1 = (const ull*)g_D1;
        ull* __restrict__ S1o = (ull*)g_S1[cur ^ 1];
        const int oidx = (c0 * 256 + (uu + 1) * 16 + (vv + 1)) * PB + u_;
#pragma unroll
        for (int r = 0; r < 8; r++) {
            int ii = oidx + r * (256 * PB);
            ulonglong2 si = ld2(S1i + ii), d1 = ld2(D1 + ii);
            ulonglong2 o;
            o.x = mul2(add2(add2(si.x, d1.x), ax[r]), half);
            o.y = mul2(add2(add2(si.y, d1.y), ay[r]), half);
            st2(S1o + ii, o);
        }
    } else if (bx < K3_BASE) {
        // ---------------- K2: s2' = 0.5*(s2 + conv2(s1)+b2 + tconv3(s3)) ----------------
        int idx = bx - K2_BASE;
        const int bb = idx & 3; idx >>= 2;
        const int pos = idx % 49;
        const int o0 = (idx / 49) * 8;
        const int u_ = bb * 512 + 2 * tid;
        float* ws2 = smf;  // conv2 weights, plain
        ull*   ws3 = smw;  // tconv3 weights, duplicated

        for (int i = tid; i < 288; i += 256) {
            const float* src = &g_w2b[i * 64 + o0];
            float* dst = &ws2[i * 8];
#pragma unroll
            for (int r = 0; r < 8; r++) dst[r] = src[r];
        }
        for (int i = tid; i < 576; i += 256) {
            const float* src = &g_w3b[i * 64 + o0];
            ull* dst = &ws3[i * 8];
#pragma unroll
            for (int r = 0; r < 8; r++) dst[r] = pk(src[r]);
        }
        __syncthreads();

        const int p = pos / 7, q = pos % 7;
        ull ax[8], ay[8];
#pragma unroll
        for (int r = 0; r < 8; r++) { ax[r] = 0ull; ay[r] = 0ull; }

        // conv2(s1): stride 2, branchless (padded 16x16)
        {
            int off[9];
#pragma unroll
            for (int di = 0; di < 3; di++)
#pragma unroll
                for (int dj = 0; dj < 3; dj++)
                    off[di * 3 + dj] = ((2 * p + di) * 16 + (2 * q + dj)) * PB;
            const ull* __restrict__ S1 = (const ull*)g_S1[cur];
#pragma unroll 2
            for (int c = 0; c < 32; c++) {
                const ull* base = S1 + c * 256 * PB + u_;
                const float* wb = ws2 + c * 72;
#pragma unroll
                for (int t = 0; t < 9; t++) {
                    ulonglong2 sv = ld2(base + off[t]);
                    const float* wp = wb + t * 8;
#pragma unroll
                    for (int r = 0; r < 8; r++) {
                        ull w2p = pk(wp[r]);
                        ax[r] = fma2(sv.x, w2p, ax[r]);
                        ay[r] = fma2(sv.y, w2p, ay[r]);
                    }
                }
            }
        }
        // tconv3(s3): flipped taps, branchless (padded 9x9)
        {
            int off[9];
#pragma unroll
            for (int di = 0; di < 3; di++)
#pragma unroll
                for (int dj = 0; dj < 3; dj++)
                    off[di * 3 + dj] = ((p + 2 - di) * 9 + (q + 2 - dj)) * PB;
            const ull* __restrict__ S3 = (const ull*)g_S3[cur];
#pragma unroll 2
            for (int m = 0; m < 64; m++) {
                const ull* base = S3 + m * 81 * PB + u_;
                const ull* wb = ws3 + m * 72;
#pragma unroll
                for (int t = 0; t < 9; t++) {
                    ulonglong2 sv = ld2(base + off[t]);
                    const ull* wp = wb + t * 8;
#pragma unroll
                    for (int r = 0; r < 8; r++) { ax[r] = fma2(sv.x, wp[r], ax[r]); ay[r] = fma2(sv.y, wp[r], ay[r]); }
                }
            }
        }

        const ull* __restrict__ S2i = (const ull*)g_S2[cur];
        ull* __restrict__ outp = (ull*)g_S2[cur ^ 1];
        const int oidx = (o0 * 81 + (p + 1) * 9 + (q + 1)) * PB + u_;
#pragma unroll
        for (int r = 0; r < 8; r++) {
            int ii = oidx + r * (81 * PB);
            ull bias = pk(b2[o0 + r]);
            ulonglong2 si = ld2(S2i + ii);
            ulonglong2 o;
            o.x = mul2(add2(add2(si.x, ax[r]), bias), half);
            o.y = mul2(add2(add2(si.y, ay[r]), bias), half);
            st2(outp + ii, o);
        }
    } else {
        // ---------------- K3: s3' = 0.5*(s3 + conv3(s2)+b3 + W4^T s4) ----------------
        int idx = bx - K3_BASE;
        const int bb = idx & 3; idx >>= 2;
        const int pos = idx % 49;
        const int c0 = (idx / 49) * 8;
        const int u_ = bb * 512 + 2 * tid;
        ull*   ws3 = smw;  // conv3 weights, duplicated
        float* ws4 = smf;  // W4 slice, plain

        for (int i = tid; i < 576; i += 256) {
            const float* src = &g_w3a[i * 64 + c0];
            ull* dst = &ws3[i * 8];
#pragma unroll
            for (int r = 0; r < 8; r++) dst[r] = pk(src[r]);
        }
        for (int j = tid; j < 256; j += 256) {
            const float* src = &g_w4r[(pos * 256 + j) * 64 + c0];
            float* dst = &ws4[j * 8];
#pragma unroll
            for (int r = 0; r < 8; r++) dst[r] = src[r];
        }
        __syncthreads();

        const int p = pos / 7, q = pos % 7;
        ull ax[8], ay[8];
#pragma unroll
        for (int r = 0; r < 8; r++) { ax[r] = 0ull; ay[r] = 0ull; }

        // conv3(s2): stride 1, branchless (padded 9x9)
        {
            int off[9];
#pragma unroll
            for (int di = 0; di < 3; di++)
#pragma unroll
                for (int dj = 0; dj < 3; dj++)
                    off[di * 3 + dj] = ((p + di) * 9 + (q + dj)) * PB;
            const ull* __restrict__ S2 = (const ull*)g_S2[cur];
#pragma unroll 2
            for (int o = 0; o < 64; o++) {
                const ull* base = S2 + o * 81 * PB + u_;
                const ull* wb = ws3 + o * 72;
#pragma unroll
                for (int t = 0; t < 9; t++) {
                    ulonglong2 sv = ld2(base + off[t]);
                    const ull* wp = wb + t * 8;
#pragma unroll
                    for (int r = 0; r < 8; r++) { ax[r] = fma2(sv.x, wp[r], ax[r]); ay[r] = fma2(sv.y, wp[r], ay[r]); }
                }
            }
        }
        // W4^T s4
        {
            const ull* __restrict__ S4 = (const ull*)g_S4[cur];
#pragma unroll 2
            for (int j = 0; j < 256; j++) {
                ulonglong2 sv = ld2(S4 + j * PB + u_);
                const float* wp = &ws4[j * 8];
#pragma unroll
                for (int r = 0; r < 8; r++) {
                    ull w4p = pk(wp[r]);
                    ax[r] = fma2(sv.x, w4p, ax[r]);
                    ay[r] = fma2(sv.y, w4p, ay[r]);
                }
            }
        }

        const ull* __restrict__ S3i = (const ull*)g_S3[cur];
        ull* __restrict__ outp = (ull*)g_S3[cur ^ 1];
        const int oidx = (c0 * 81 + (p + 1) * 9 + (q + 1)) * PB + u_;
#pragma unroll
        for (int r = 0; r < 8; r++) {
            int ii = oidx + r * (81 * PB);
            ull bias = pk(b3[c0 + r]);
            ulonglong2 si = ld2(S3i + ii);
            ulonglong2 o;
            o.x = mul2(add2(add2(si.x, ax[r]), bias), half);
            o.y = mul2(add2(add2(si.y, ay[r]), bias), half);
            st2(outp + ii, o);
        }
    }
}

// ============================================================================
// Forward-only kernels for energy readout (run once)
// ============================================================================
__global__ void __launch_bounds__(256) fwd2_kernel(int cur, const float* __restrict__ b2) {
    __shared__ float ws2[288 * 8];
    const int tid = threadIdx.x;
    const int o0 = blockIdx.z * 8;
    for (int i = tid; i < 288; i += 256) {
        const float* src = &g_w2b[i * 64 + o0];
        float* dst = &ws2[i * 8];
#pragma unroll
        for (int r = 0; r < 8; r++) dst[r] = src[r];
    }
    __syncthreads();

    const int bp = blockIdx.x * 256 + tid;
    const int pos = blockIdx.y;
    const int p = pos / 7, q = pos % 7;

    ull acc[8];
#pragma unroll
    for (int r = 0; r < 8; r++) acc[r] = 0ull;

    int off[9];
#pragma unroll
    for (int di = 0; di < 3; di++)
#pragma unroll
        for (int dj = 0; dj < 3; dj++)
            off[di * 3 + dj] = ((2 * p + di) * 16 + (2 * q + dj)) * PB;
    const ull* __restrict__ S1 = (const ull*)g_S1[cur];
#pragma unroll 2
    for (int c = 0; c < 32; c++) {
        const ull* base = S1 + c * 256 * PB + bp;
        const float* wb = ws2 + c * 72;
#pragma unroll
        for (int t = 0; t < 9; t++) {
            ull sv = base[off[t]];
            const float* wp = wb + t * 8;
#pragma unroll
            for (int r = 0; r < 8; r++) acc[r] = fma2(sv, pk(wp[r]), acc[r]);
        }
    }

    ull* __restrict__ outp = (ull*)g_S2[cur ^ 1];
    const int oidx = (o0 * 81 + (p + 1) * 9 + (q + 1)) * PB + bp;
#pragma unroll
    for (int r = 0; r < 8; r++) outp[oidx + r * (81 * PB)] = add2(acc[r], pk(b2[o0 + r]));
}

__global__ void __launch_bounds__(256) fwd3_kernel(int cur, const float* __restrict__ b3) {
    __shared__ ull ws3[576 * 8];
    const int tid = threadIdx.x;
    const int c0 = blockIdx.z * 8;
    const int pos = blockIdx.y;
    for (int i = tid; i < 576; i += 256) {
        const float* src = &g_w3a[i * 64 + c0];
        ull* dst = &ws3[i * 8];
#pragma unroll
        for (int r = 0; r < 8; r++) dst[r] = pk(src[r]);
    }
    __syncthreads();

    const int bp = blockIdx.x * 256 + tid;
    const int p = pos / 7, q = pos % 7;

    ull acc[8];
#pragma unroll
    for (int r = 0; r < 8; r++) acc[r] = 0ull;

    int off[9];
#pragma unroll
    for (int di = 0; di < 3; di++)
#pragma unroll
        for (int dj = 0; dj < 3; dj++)
            off[di * 3 + dj] = ((p + di) * 9 + (q + dj)) * PB;
    const ull* __restrict__ S2 = (const ull*)g_S2[cur];
#pragma unroll 2
    for (int o = 0; o < 64; o++) {
        const ull* base = S2 + o * 81 * PB + bp;
        const ull* wb = ws3 + o * 72;
#pragma unroll
        for (int t = 0; t < 9; t++) {
            ull sv = base[off[t]];
            const ull* wp = wb + t * 8;
#pragma unroll
            for (int r = 0; r < 8; r++) acc[r] = fma2(sv, wp[r], acc[r]);
        }
    }

    ull* __restrict__ outp = (ull*)g_S3[cur ^ 1];
    const int oidx = (c0 * 81 + (p + 1) * 9 + (q + 1)) * PB + bp;
#pragma unroll
    for (int r = 0; r < 8; r++) outp[oidx + r * (81 * PB)] = add2(acc[r], pk(b3[c0 + r]));
}

__global__ void __launch_bounds__(256) fwd4_kernel(int cur, const float* __restrict__ b4) {
    __shared__ ull ws[392 * 8];
    const int tid = threadIdx.x;
    const int j0 = blockIdx.y * 8;
    const int bp = blockIdx.x * 256 + tid;
    const ull* __restrict__ S3 = (const ull*)g_S3[cur];

    ull acc[8];
#pragma unroll
    for (int r = 0; r < 8; r++) acc[r] = 0ull;

    for (int ch = 0; ch < 8; ch++) {
        __syncthreads();
        for (int i = tid; i < 392; i += 256) {
            const float* src = &g_w4t[(ch * 392 + i) * 256 + j0];
            ull* dst = &ws[i * 8];
#pragma unroll
            for (int r = 0; r < 8; r++) dst[r] = pk(src[r]);
        }
        __syncthreads();
        for (int cc = 0; cc < 8; cc++) {
            const ull* cb = S3 + ((ch * 8 + cc) * 81) * PB + bp;
            const ull* wch = ws + cc * 392;
            int kk = 0;
#pragma unroll
            for (int pp = 1; pp <= 7; pp++) {
#pragma unroll
                for (int qq = 1; qq <= 7; qq++) {
                    ull sv = cb[(pp * 9 + qq) * PB];
                    const ull* wp = wch + kk * 8; kk++;
#pragma unroll
                    for (int r = 0; r < 8; r++) acc[r] = fma2(sv, wp[r], acc[r]);
                }
            }
        }
    }

    ull* __restrict__ outp = (ull*)g_S4[cur ^ 1];
#pragma unroll
    for (int r = 0; r < 8; r++) outp[(j0 + r) * PB + bp] = add2(acc[r], pk(b4[j0 + r]));
}

// ---------------- energy readout ----------------
__global__ void energy_zero(float* __restrict__ out) {
    int b = blockIdx.x * 256 + threadIdx.x;
    out[b] = 0.f;
}

__global__ void energy_partial(const float* __restrict__ vb, int fin,
                               float* __restrict__ out) {
    const int b = blockIdx.x * 256 + threadIdx.x;
    const int s = blockIdx.y;  // 0..7
    const float* __restrict__ S1 = g_S1[fin];
    const float* __restrict__ S2 = g_S2[fin];
    const float* __restrict__ S3 = g_S3[fin];
    const float* __restrict__ S4 = g_S4[fin];
    const float* __restrict__ F2 = g_S2[fin ^ 1];
    const float* __restrict__ F3 = g_S3[fin ^ 1];
    const float* __restrict__ F4 = g_S4[fin ^ 1];

    double e = 0.0;
    if (s == 0) {
        for (int p = 0; p < 784; p++) {
            float xv = g_XT[p * BB + b];
            float term = 0.5f * xv * xv - vb[p] * xv;
            e += (double)term;
        }
        for (int i = 0; i < 256; i++) {
            float sv = S4[i * BB + b];
            float term = 0.5f * sv * sv - sv * F4[i * BB + b];
            e += (double)term;
        }
    }
    // S1 interior: 4 channels per slice
    for (int c = s * 4; c < s * 4 + 4; c++) {
        const float* Sr = S1 + c * 256 * BB;
        const float* Dr = g_D1 + c * 256 * BB;
        for (int pp = 1; pp <= 14; pp++)
            for (int vv = 1; vv <= 14; vv++) {
                int ro = (pp * 16 + vv) * BB + b;
                float sv = Sr[ro];
                float term = 0.5f * sv * sv - sv * Dr[ro];
                e += (double)term;
            }
    }
    if (s < 4) {
        for (int c = s * 16; c < s * 16 + 16; c++) {
            const float* Sr = S2 + c * 81 * BB;
            const float* Fr = F2 + c * 81 * BB;
            for (int pp = 1; pp <= 7; pp++)
                for (int qq = 1; qq <= 7; qq++) {
                    int ro = (pp * 9 + qq) * BB + b;
                    float sv = Sr[ro];
                    float term = 0.5f * sv * sv - sv * Fr[ro];
                    e += (double)term;
                }
        }
    } else {
        for (int c = (s - 4) * 16; c < (s - 4) * 16 + 16; c++) {
            const float* Sr = S3 + c * 81 * BB;
            const float* Fr = F3 + c * 81 * BB;
            for (int pp = 1; pp <= 7; pp++)
                for (int qq = 1; qq <= 7; qq++) {
                    int ro = (pp * 9 + qq) * BB + b;
                    float sv = Sr[ro];
                    float term = 0.5f * sv * sv - sv * Fr[ro];
                    e += (double)term;
                }
        }
    }
    atomicAdd(&out[b], (float)e);
}

// ---------------- launcher ----------------
extern "C" void kernel_launch(void* const* d_in, const int* in_sizes, int n_in,
                              void* d_out, int out_size) {
    const float* x  = (const float*)d_in[0];
    const float* vb = (const float*)d_in[1];
    const float* w1 = (const float*)d_in[2];
    const float* b1 = (const float*)d_in[3];
    const float* w2 = (const float*)d_in[4];
    const float* b2 = (const float*)d_in[5];
    const float* w3 = (const float*)d_in[6];
    const float* b3 = (const float*)d_in[7];
    const float* w4 = (const float*)d_in[8];
    const float* b4 = (const float*)d_in[9];
    float* out = (float*)d_out;

    zero_state<<<4096, 256>>>();
    transpose_x<<<dim3(25, 128), dim3(32, 8)>>>(x);
    prep_weights<<<1024, 256>>>(w2, w3, w4);
    compute_d1<<<dim3(16, 196, 32), 256>>>(w1, b1);

    int cur = 0;
    for (int t = 0; t < 50; t++) {
        step_kernel<<<STEP_GRID, 256>>>(cur, b2, b3, b4);
        cur ^= 1;
    }

    // forward-only passes at the fixed point into the free ping-pong buffers
    fwd2_kernel<<<dim3(8, 49, 8), 256>>>(cur, b2);
    fwd3_kernel<<<dim3(8, 49, 8), 256>>>(cur, b3);
    fwd4_kernel<<<dim3(8, 32, 1), 256>>>(cur, b4);

    energy_zero<<<16, 256>>>(out);
    energy_partial<<<dim3(16, 8), 256>>>(vb, cur, out);
}